// round 10
// baseline (speedup 1.0000x reference)
#include <cuda_runtime.h>
#include <cuda_bf16.h>
#include <math.h>
#include <stdint.h>

#define BATCH 2
#define SEQL  2048
#define DMODEL 768
#define NH    12
#define HD    64
#define KSEL  46
#define NKV   1536
#define NROWS (BATCH*SEQL)
#define WQKV_COLS 2304
#define NQ    (BATCH*KSEL)
#define NQP   96
#define CH    64
#define NCH   (SEQL/CH)

// -------- scratch --------
__device__ float g_p1[NROWS];
__device__ int   g_idx[NQ];
__device__ int   g_cnt[BATCH];
__device__ float g_kv[(size_t)NROWS * NKV];
__device__ float g_q[NQP*DMODEL];
__device__ float g_ctx[NQP*DMODEL];
__device__ float g_pm[BATCH*NH*NCH*48];
__device__ float g_pl[BATCH*NH*NCH*48];
__device__ float g_po[(size_t)BATCH*NH*NCH*48*HD];
__device__ __nv_bfloat16 g_xb[(size_t)NROWS * DMODEL];   // X bf16 [row][k]
__device__ __nv_bfloat16 g_wt[(size_t)NKV * DMODEL];     // W_kv bf16 [n][k]

__device__ __forceinline__ uint32_t smem_u32(const void* p) {
    uint32_t a;
    asm("{ .reg .u64 t; cvta.to.shared.u64 t, %1; cvt.u32.u64 %0, t; }" : "=r"(a) : "l"(p));
    return a;
}
__device__ __forceinline__ void ldm_x4(uint32_t* r, uint32_t addr) {
    asm volatile("ldmatrix.sync.aligned.m8n8.x4.shared.b16 {%0,%1,%2,%3}, [%4];"
        : "=r"(r[0]), "=r"(r[1]), "=r"(r[2]), "=r"(r[3]) : "r"(addr));
}
__device__ __forceinline__ void mma16816(float* c, const uint32_t* a, uint32_t b0, uint32_t b1) {
    asm volatile(
        "mma.sync.aligned.m16n8k16.row.col.f32.bf16.bf16.f32 "
        "{%0,%1,%2,%3}, {%4,%5,%6,%7}, {%8,%9}, {%0,%1,%2,%3};"
        : "+f"(c[0]), "+f"(c[1]), "+f"(c[2]), "+f"(c[3])
        : "r"(a[0]), "r"(a[1]), "r"(a[2]), "r"(a[3]), "r"(b0), "r"(b1));
}
#define CP_ASYNC16(dst, src) \
    asm volatile("cp.async.cg.shared.global [%0], [%1], 16;" :: "r"(dst), "l"(src))
#define CP_COMMIT() asm volatile("cp.async.commit_group;" ::: "memory")
#define CP_WAIT1()  asm volatile("cp.async.wait_group 1;" ::: "memory")

// ============================================================================
// sel prob + y=x copy + x->bf16 convert; first blocks also zero g_q / g_cnt.
// ============================================================================
__global__ void sel_copy_kernel(const float* __restrict__ x,
                                const float* __restrict__ sel_w,
                                const float* __restrict__ sel_b,
                                const float* __restrict__ temp,
                                float* __restrict__ y) {
    int r = blockIdx.x;
    int tid = threadIdx.x;
    // zero scratch: NQP*DMODEL = 73728 floats; 288 blocks x 256 thr x 1 float
    if (r < 288) {
        int i = r * 256 + tid;
        g_q[i] = 0.f;
        if (i < BATCH) g_cnt[i] = 0;
    }
    const float* xr = x + (size_t)r * DMODEL;
    float* yr = y + (size_t)r * DMODEL;
    __nv_bfloat16* xb = g_xb + (size_t)r * DMODEL;
    float p0 = 0.f, p1 = 0.f;
    #pragma unroll
    for (int j = tid; j < DMODEL; j += 256) {
        float v = xr[j];
        yr[j] = v;
        xb[j] = __float2bfloat16(v);
        float2 w = *(const float2*)&sel_w[2*j];
        p0 = fmaf(v, w.x, p0);
        p1 = fmaf(v, w.y, p1);
    }
    #pragma unroll
    for (int off = 16; off; off >>= 1) {
        p0 += __shfl_down_sync(0xffffffffu, p0, off);
        p1 += __shfl_down_sync(0xffffffffu, p1, off);
    }
    __shared__ float s0[8], s1[8];
    int w = tid >> 5;
    if ((tid & 31) == 0) { s0[w] = p0; s1[w] = p1; }
    __syncthreads();
    if (tid == 0) {
        float a0 = 0.f, a1 = 0.f;
        #pragma unroll
        for (int i = 0; i < 8; i++) { a0 += s0[i]; a1 += s1[i]; }
        a0 += sel_b[0]; a1 += sel_b[1];
        float d = (a1 - a0) / temp[0];
        g_p1[r] = 1.0f / (1.0f + expf(-d));
    }
}

// ============================================================================
// W_kv (cols 768:2304) -> g_wt[n][k] bf16 (transpose)
// ============================================================================
__global__ void w_transpose_kernel(const float* __restrict__ W) {
    __shared__ float t[32][33];
    int n0 = blockIdx.x * 32;
    int k0 = blockIdx.y * 32;
    int tx = threadIdx.x, ty = threadIdx.y;
    #pragma unroll
    for (int i = 0; i < 4; i++)
        t[ty + 8*i][tx] = W[(size_t)(k0 + ty + 8*i) * WQKV_COLS + 768 + n0 + tx];
    __syncthreads();
    #pragma unroll
    for (int i = 0; i < 4; i++)
        g_wt[(size_t)(n0 + ty + 8*i) * DMODEL + k0 + tx] = __float2bfloat16(t[tx][ty + 8*i]);
}

// ============================================================================
// KV GEMM: cp.async 3-stage pipeline + swizzled smem + mma.sync.
// CTA 128x128, 8 warps (2M x 4N), K-chunk 32.
// SMEM: logical (r, u16B) -> byte (r>>1)*128 + ((((r&1)<<2)|u) ^ ((r>>1)&7))*16
// ============================================================================
#define STAGE_BYTES 8192   // 64 phys rows * 128 B

__global__ void __launch_bounds__(256) kv_mma_kernel(const float* __restrict__ bias) {
    __shared__ __align__(128) __nv_bfloat16 sA[3*4096];   // 24 KB
    __shared__ __align__(128) __nv_bfloat16 sB[3*4096];   // 24 KB
    int tid = threadIdx.x;
    int wid = tid >> 5, lane = tid & 31;
    int wm = wid & 1, wn = wid >> 1;
    int g = lane >> 2, tg = lane & 3;
    int row0 = blockIdx.y * 128;
    int col0 = blockIdx.x * 128;
    uint32_t baseA = smem_u32(sA), baseB = smem_u32(sB);

    // cp.async loader: unit gu = tid&3, rows gr and gr+64
    int gr = tid >> 2;
    int gu = tid & 3;
    int par = gr & 1;
    int prow0 = gr >> 1;
    int su = ((par << 2) | gu) ^ (prow0 & 7);
    uint32_t stA = baseA + (uint32_t)(prow0 * 128 + su * 16);
    uint32_t stB = baseB + (uint32_t)(prow0 * 128 + su * 16);
    const __nv_bfloat16* gA0 = g_xb + (size_t)(row0 + gr) * DMODEL + gu * 8;
    const __nv_bfloat16* gA1 = g_xb + (size_t)(row0 + gr + 64) * DMODEL + gu * 8;
    const __nv_bfloat16* gB0 = g_wt + (size_t)(col0 + gr) * DMODEL + gu * 8;
    const __nv_bfloat16* gB1 = g_wt + (size_t)(col0 + gr + 64) * DMODEL + gu * 8;

    // ldmatrix lane constants
    int lrow = lane & 15, lsb = lane >> 4;
    int mrA = wm * 64 + lrow;
    int prA = mrA >> 1, paA = (mrA & 1) << 2, xa = prA & 7;
    int nrB = wn * 32 + lrow;
    int prB = nrB >> 1, paB = (nrB & 1) << 2, xb = prB & 7;

    float c[4][4][4];
    #pragma unroll
    for (int mi = 0; mi < 4; mi++)
        #pragma unroll
        for (int ni = 0; ni < 4; ni++)
            #pragma unroll
            for (int j = 0; j < 4; j++) c[mi][ni][j] = 0.f;

    // prologue: stages 0, 1
    #pragma unroll
    for (int s = 0; s < 2; s++) {
        uint32_t so = (uint32_t)(s * STAGE_BYTES);
        int k0 = s * 32;
        CP_ASYNC16(stA + so, gA0 + k0);          CP_ASYNC16(stA + so + 32*128, gA1 + k0);
        CP_ASYNC16(stB + so, gB0 + k0);          CP_ASYNC16(stB + so + 32*128, gB1 + k0);
        CP_COMMIT();
    }

    int slot = 0;        // kc % 3
    int nslot = 2;       // (kc+2) % 3
    for (int kc = 0; kc < 24; kc++) {
        CP_WAIT1();
        __syncthreads();
        if (kc + 2 < 24) {
            int k0 = (kc + 2) * 32;
            uint32_t so = (uint32_t)(nslot * STAGE_BYTES);
            CP_ASYNC16(stA + so, gA0 + k0);      CP_ASYNC16(stA + so + 32*128, gA1 + k0);
            CP_ASYNC16(stB + so, gB0 + k0);      CP_ASYNC16(stB + so + 32*128, gB1 + k0);
        }
        CP_COMMIT();     // unconditional: keeps group numbering advancing in tail
        uint32_t so = (uint32_t)(slot * STAGE_BYTES);
        #pragma unroll
        for (int ks = 0; ks < 2; ks++) {
            int u = ks * 2 + lsb;
            uint32_t offA = (uint32_t)(((paA | u) ^ xa) << 4);
            uint32_t offB = (uint32_t)(((paB | u) ^ xb) << 4);
            uint32_t A[4][4], Bf[2][4];
            #pragma unroll
            for (int mi = 0; mi < 4; mi++)
                ldm_x4(A[mi], baseA + so + (uint32_t)((prA + mi*8) * 128) + offA);
            #pragma unroll
            for (int bi = 0; bi < 2; bi++)
                ldm_x4(Bf[bi], baseB + so + (uint32_t)((prB + bi*8) * 128) + offB);
            #pragma unroll
            for (int mi = 0; mi < 4; mi++) {
                mma16816(c[mi][0], A[mi], Bf[0][0], Bf[0][2]);
                mma16816(c[mi][1], A[mi], Bf[0][1], Bf[0][3]);
                mma16816(c[mi][2], A[mi], Bf[1][0], Bf[1][2]);
                mma16816(c[mi][3], A[mi], Bf[1][1], Bf[1][3]);
            }
        }
        slot = (slot + 1) % 3;
        nslot = (nslot + 1) % 3;
    }

    #pragma unroll
    for (int mi = 0; mi < 4; mi++) {
        int row = row0 + wm * 64 + mi * 16;
        #pragma unroll
        for (int ni = 0; ni < 4; ni++) {
            int col = col0 + wn * 32 + ni * 8 + 2 * tg;
            float2 bb = *(const float2*)&bias[768 + col];
            float2 r0, r1;
            r0.x = c[mi][ni][0] + bb.x; r0.y = c[mi][ni][1] + bb.y;
            r1.x = c[mi][ni][2] + bb.x; r1.y = c[mi][ni][3] + bb.y;
            *(float2*)&g_kv[(size_t)(row + g) * NKV + col] = r0;
            *(float2*)&g_kv[(size_t)(row + g + 8) * NKV + col] = r1;
        }
    }
}

// ============================================================================
// rank-select top-KSEL (jax tie-break); slot order irrelevant downstream.
// ============================================================================
__global__ void __launch_bounds__(256) ranksel_kernel() {
    int b = blockIdx.y;
    __shared__ float vals[SEQL];
    int tid = threadIdx.x;
    int warp = tid >> 5, lane = tid & 31;
    #pragma unroll
    for (int l = 0; l < 8; l++) vals[tid + l * 256] = g_p1[b * SEQL + tid + l * 256];
    __syncthreads();
    #pragma unroll
    for (int i = 0; i < 8; i++) {
        int cand = blockIdx.x * 64 + warp * 8 + i;
        float v = vals[cand];
        int cnt = 0;
        #pragma unroll
        for (int l = 0; l < 64; l++) {
            int j = lane + l * 32;
            float u = vals[j];
            cnt += (u > v || (u == v && j < cand)) ? 1 : 0;
        }
        #pragma unroll
        for (int off = 16; off; off >>= 1)
            cnt += __shfl_xor_sync(0xffffffffu, cnt, off);
        if (lane == 0 && cnt < KSEL) {
            int slot = atomicAdd(&g_cnt[b], 1);
            g_idx[b * KSEL + slot] = cand;
        }
    }
}

// ============================================================================
// Q projection: gathered rows from x, k-split (z), atomicAdd into zeroed g_q.
// ============================================================================
__global__ void __launch_bounds__(256) qproj_kernel(const float* __restrict__ x,
                                                    const float* __restrict__ W,
                                                    const float* __restrict__ bias) {
    __shared__ float As[64*48];
    __shared__ float Bs[64*64];
    __shared__ int rowsrc[48];
    int tid = threadIdx.x;
    int tx = tid & 15, ty = tid >> 4;
    int cb = blockIdx.x * 64;
    int rt = blockIdx.y;
    int kb = blockIdx.z * 64;
    if (tid < 48) {
        int r = rt*48 + tid;
        rowsrc[tid] = (r < NQ) ? ((r / KSEL) * SEQL + g_idx[r]) : -1;
    }
    __syncthreads();

    #pragma unroll
    for (int l = 0; l < 3; l++) {
        int fid = tid + l*256;
        int row = fid >> 4;
        int kc  = (fid & 15) << 2;
        int src = rowsrc[row];
        float4 v = make_float4(0.f, 0.f, 0.f, 0.f);
        if (src >= 0) v = *(const float4*)&x[(size_t)src*DMODEL + kb + kc];
        As[(kc+0)*48 + row] = v.x; As[(kc+1)*48 + row] = v.y;
        As[(kc+2)*48 + row] = v.z; As[(kc+3)*48 + row] = v.w;
    }
    #pragma unroll
    for (int l = 0; l < 4; l++) {
        int fid = tid + l*256;
        int kr = fid >> 4;
        int c4 = (fid & 15) << 2;
        *(float4*)&Bs[kr*64 + c4] = *(const float4*)&W[(size_t)(kb + kr)*WQKV_COLS + cb + c4];
    }
    __syncthreads();
    float acc[3][4];
    #pragma unroll
    for (int i = 0; i < 3; i++)
        #pragma unroll
        for (int j = 0; j < 4; j++) acc[i][j] = 0.f;
    #pragma unroll 8
    for (int k = 0; k < 64; k++) {
        float4 bv = *(const float4*)&Bs[k*64 + tx*4];
        #pragma unroll
        for (int i = 0; i < 3; i++) {
            float a = As[k*48 + ty*3 + i];
            acc[i][0] = fmaf(a, bv.x, acc[i][0]);
            acc[i][1] = fmaf(a, bv.y, acc[i][1]);
            acc[i][2] = fmaf(a, bv.z, acc[i][2]);
            acc[i][3] = fmaf(a, bv.w, acc[i][3]);
        }
    }
    #pragma unroll
    for (int i = 0; i < 3; i++) {
        int row = rt*48 + ty*3 + i;
        if (row < NQ) {
            #pragma unroll
            for (int j = 0; j < 4; j++) {
                int col = cb + tx*4 + j;
                float v = acc[i][j] + (blockIdx.z == 0 ? bias[col] : 0.f);
                atomicAdd(&g_q[(size_t)row*DMODEL + col], v);
            }
        }
    }
}

// ============================================================================
// flash-decode attention chunk (fp32)
// ============================================================================
__global__ void __launch_bounds__(256) attn_chunk_kernel() {
    int c  = blockIdx.x;
    int h  = blockIdx.y;
    int b  = blockIdx.z;
    int c0 = c * CH;
    int tid = threadIdx.x;
    int tx = tid & 15, ty = tid >> 4;

    __shared__ float qs[48*HD];
    __shared__ float kv_s[CH*HD];
    __shared__ float S[48*66];
    __shared__ int   ts[48];

    if (tid < 48) ts[tid] = (tid < KSEL) ? g_idx[b*KSEL + tid] : -1;
    for (int idx = tid; idx < 48*HD; idx += 256) {
        int q = idx >> 6, d = idx & 63;
        qs[idx] = (q < KSEL) ? g_q[(size_t)(b*KSEL + q)*DMODEL + h*HD + d] * 0.125f : 0.f;
    }
    const float* kvb = g_kv + (size_t)b * SEQL * NKV;
    #pragma unroll
    for (int l = 0; l < 4; l++) {
        int fid = tid + l*256;
        int key = fid >> 4;
        int dq  = (fid & 15) << 2;
        float4 v = *(const float4*)&kvb[(size_t)(c0 + key)*NKV + h*HD + dq];
        kv_s[(dq+0)*CH + key] = v.x; kv_s[(dq+1)*CH + key] = v.y;
        kv_s[(dq+2)*CH + key] = v.z; kv_s[(dq+3)*CH + key] = v.w;
    }
    __syncthreads();

    float acc[3][4];
    #pragma unroll
    for (int i = 0; i < 3; i++)
        #pragma unroll
        for (int j = 0; j < 4; j++) acc[i][j] = 0.f;
    #pragma unroll 8
    for (int d = 0; d < HD; d++) {
        float4 bv = *(const float4*)&kv_s[d*CH + tx*4];
        #pragma unroll
        for (int i = 0; i < 3; i++) {
            float a = qs[(ty*3+i)*HD + d];
            acc[i][0] = fmaf(a, bv.x, acc[i][0]);
            acc[i][1] = fmaf(a, bv.y, acc[i][1]);
            acc[i][2] = fmaf(a, bv.z, acc[i][2]);
            acc[i][3] = fmaf(a, bv.w, acc[i][3]);
        }
    }
    #pragma unroll
    for (int i = 0; i < 3; i++) {
        int q = ty*3 + i;
        int tq = ts[q];
        #pragma unroll
        for (int j = 0; j < 4; j++) {
            int sg = c0 + tx*4 + j;
            S[q*66 + tx*4 + j] = (q < KSEL && sg <= tq) ? acc[i][j] : -1e30f;
        }
    }
    __syncthreads();

    #pragma unroll
    for (int l = 0; l < 4; l++) {
        int fid = tid + l*256;
        int key = fid >> 4;
        int dq  = (fid & 15) << 2;
        *(float4*)&kv_s[key*HD + dq] =
            *(const float4*)&kvb[(size_t)(c0 + key)*NKV + DMODEL + h*HD + dq];
    }
    if (tid < 48) {
        int q = tid;
        float m = -1e30f;
        #pragma unroll 8
        for (int k = 0; k < CH; k++) m = fmaxf(m, S[q*66 + k]);
        float l = 0.f;
        #pragma unroll 8
        for (int k = 0; k < CH; k++) {
            float v = S[q*66 + k];
            float p = (v > -1e29f) ? __expf(v - m) : 0.f;
            S[q*66 + k] = p;
            l += p;
        }
        int base = ((b*NH + h)*NCH + c)*48 + q;
        g_pm[base] = m;
        g_pl[base] = l;
    }
    __syncthreads();

    float acc2[3][4];
    #pragma unroll
    for (int i = 0; i < 3; i++)
        #pragma unroll
        for (int j = 0; j < 4; j++) acc2[i][j] = 0.f;
    #pragma unroll 8
    for (int k = 0; k < CH; k++) {
        float4 bv = *(const float4*)&kv_s[k*HD + tx*4];
        #pragma unroll
        for (int i = 0; i < 3; i++) {
            float a = S[(ty*3+i)*66 + k];
            acc2[i][0] = fmaf(a, bv.x, acc2[i][0]);
            acc2[i][1] = fmaf(a, bv.y, acc2[i][1]);
            acc2[i][2] = fmaf(a, bv.z, acc2[i][2]);
            acc2[i][3] = fmaf(a, bv.w, acc2[i][3]);
        }
    }
    size_t obase = ((size_t)((b*NH + h)*NCH + c))*48;
    #pragma unroll
    for (int i = 0; i < 3; i++) {
        float4 r; r.x = acc2[i][0]; r.y = acc2[i][1]; r.z = acc2[i][2]; r.w = acc2[i][3];
        *(float4*)&g_po[(obase + ty*3 + i)*HD + tx*4] = r;
    }
}

// ============================================================================
__global__ void attn_combine_kernel() {
    int bx = blockIdx.x;
    int q  = bx / NH;
    int h  = bx % NH;
    int b  = q / KSEL;
    int qi = q % KSEL;
    int d  = threadIdx.x;
    int bh = b*NH + h;

    float m = -1e30f;
    #pragma unroll
    for (int c = 0; c < NCH; c++)
        m = fmaxf(m, g_pm[(bh*NCH + c)*48 + qi]);
    float num = 0.f, den = 0.f;
    #pragma unroll
    for (int c = 0; c < NCH; c++) {
        int base = (bh*NCH + c)*48 + qi;
        float w = __expf(g_pm[base] - m);
        den = fmaf(w, g_pl[base], den);
        num = fmaf(w, g_po[(size_t)base*HD + d], num);
    }
    g_ctx[(size_t)q*DMODEL + h*HD + d] = num / den;
}

// ============================================================================
// out projection: k-split (z), gate, atomicAdd into y
// ============================================================================
__global__ void __launch_bounds__(256) outproj_kernel(const float* __restrict__ W,
                                                      const float* __restrict__ bias,
                                                      float* __restrict__ y) {
    __shared__ float As[64*48];
    __shared__ float Bs[64*64];
    int tid = threadIdx.x;
    int tx = tid & 15, ty = tid >> 4;
    int cb = blockIdx.x * 64;
    int rt = blockIdx.y;
    int kb = blockIdx.z * 64;

    #pragma unroll
    for (int l = 0; l < 3; l++) {
        int fid = tid + l*256;
        int row = fid >> 4;
        int kc  = (fid & 15) << 2;
        float4 v = *(const float4*)&g_ctx[(size_t)(rt*48 + row)*DMODEL + kb + kc];
        As[(kc+0)*48 + row] = v.x; As[(kc+1)*48 + row] = v.y;
        As[(kc+2)*48 + row] = v.z; As[(kc+3)*48 + row] = v.w;
    }
    #pragma unroll
    for (int l = 0; l < 4; l++) {
        int fid = tid + l*256;
        int kr = fid >> 4;
        int c4 = (fid & 15) << 2;
        *(float4*)&Bs[kr*64 + c4] = *(const float4*)&W[(size_t)(kb + kr)*DMODEL + cb + c4];
    }
    __syncthreads();
    float acc[3][4];
    #pragma unroll
    for (int i = 0; i < 3; i++)
        #pragma unroll
        for (int j = 0; j < 4; j++) acc[i][j] = 0.f;
    #pragma unroll 8
    for (int k = 0; k < 64; k++) {
        float4 bv = *(const float4*)&Bs[k*64 + tx*4];
        #pragma unroll
        for (int i = 0; i < 3; i++) {
            float a = As[k*48 + ty*3 + i];
            acc[i][0] = fmaf(a, bv.x, acc[i][0]);
            acc[i][1] = fmaf(a, bv.y, acc[i][1]);
            acc[i][2] = fmaf(a, bv.z, acc[i][2]);
            acc[i][3] = fmaf(a, bv.w, acc[i][3]);
        }
    }
    #pragma unroll
    for (int i = 0; i < 3; i++) {
        int row = rt*48 + ty*3 + i;
        if (row < NQ) {
            int b = row / KSEL;
            int t = g_idx[row];
            float p = g_p1[b*SEQL + t];
            float* yr = y + (size_t)(b*SEQL + t)*DMODEL;
            #pragma unroll
            for (int j = 0; j < 4; j++) {
                int col = cb + tx*4 + j;
                float v = acc[i][j] + (blockIdx.z == 0 ? bias[col] : 0.f);
                atomicAdd(&yr[col], p * v);
            }
        }
    }
}

// ============================================================================
extern "C" void kernel_launch(void* const* d_in, const int* in_sizes, int n_in,
                              void* d_out, int out_size) {
    const float* x     = (const float*)d_in[0];
    const float* Wqkv  = (const float*)d_in[1];
    const float* bqkv  = (const float*)d_in[2];
    const float* sel_w = (const float*)d_in[3];
    const float* sel_b = (const float*)d_in[4];
    const float* out_w = (const float*)d_in[5];
    const float* out_b = (const float*)d_in[6];
    const float* temp  = (const float*)d_in[7];
    float* y = (float*)d_out;

    sel_copy_kernel<<<NROWS, 256>>>(x, sel_w, sel_b, temp, y);
    w_transpose_kernel<<<dim3(NKV/32, DMODEL/32), dim3(32, 8)>>>(Wqkv);
    kv_mma_kernel<<<dim3(NKV/128, NROWS/128), 256>>>(bqkv);
    ranksel_kernel<<<dim3(SEQL/64, BATCH), 256>>>();
    qproj_kernel<<<dim3(12, 2, 12), 256>>>(x, Wqkv, bqkv);
    attn_chunk_kernel<<<dim3(NCH, NH, BATCH), 256>>>();
    attn_combine_kernel<<<NQ*NH, HD>>>();
    outproj_kernel<<<dim3(12, 2, 12), 256>>>(out_w, out_b, y);
}

// round 11
// speedup vs baseline: 1.0619x; 1.0619x over previous
#include <cuda_runtime.h>
#include <cuda_bf16.h>
#include <math.h>
#include <stdint.h>

#define BATCH 2
#define SEQL  2048
#define DMODEL 768
#define NH    12
#define HD    64
#define KSEL  46
#define NKV   1536
#define NROWS (BATCH*SEQL)
#define WQKV_COLS 2304
#define NQ    (BATCH*KSEL)
#define NQP   96
#define CH    64
#define NCH   (SEQL/CH)

// -------- scratch --------
__device__ float g_p1[NROWS];
__device__ int   g_idx[NQ];
__device__ int   g_cnt[BATCH];
__device__ float g_kv[(size_t)NROWS * NKV];
__device__ float g_q[NQP*DMODEL];
__device__ float g_ctx[NQP*DMODEL];
__device__ float g_pm[BATCH*NH*NCH*48];
__device__ float g_pl[BATCH*NH*NCH*48];
__device__ float g_po[(size_t)BATCH*NH*NCH*48*HD];
__device__ __nv_bfloat16 g_xb[(size_t)NROWS * DMODEL];   // X bf16 [row][k]
__device__ __nv_bfloat16 g_wt[(size_t)NKV * DMODEL];     // W_kv bf16 [n][k]

// -------- streams/events for capture fork-join (created once at load) ------
struct HxStreams {
    cudaStream_t s2;
    cudaEvent_t e0, eX, eK;
    HxStreams() {
        cudaStreamCreateWithFlags(&s2, cudaStreamNonBlocking);
        cudaEventCreateWithFlags(&e0, cudaEventDisableTiming);
        cudaEventCreateWithFlags(&eX, cudaEventDisableTiming);
        cudaEventCreateWithFlags(&eK, cudaEventDisableTiming);
    }
};
static HxStreams hx;

__device__ __forceinline__ uint32_t smem_u32(const void* p) {
    uint32_t a;
    asm("{ .reg .u64 t; cvta.to.shared.u64 t, %1; cvt.u32.u64 %0, t; }" : "=r"(a) : "l"(p));
    return a;
}
__device__ __forceinline__ void ldm_x4(uint32_t* r, uint32_t addr) {
    asm volatile("ldmatrix.sync.aligned.m8n8.x4.shared.b16 {%0,%1,%2,%3}, [%4];"
        : "=r"(r[0]), "=r"(r[1]), "=r"(r[2]), "=r"(r[3]) : "r"(addr));
}
__device__ __forceinline__ void mma16816(float* c, const uint32_t* a, uint32_t b0, uint32_t b1) {
    asm volatile(
        "mma.sync.aligned.m16n8k16.row.col.f32.bf16.bf16.f32 "
        "{%0,%1,%2,%3}, {%4,%5,%6,%7}, {%8,%9}, {%0,%1,%2,%3};"
        : "+f"(c[0]), "+f"(c[1]), "+f"(c[2]), "+f"(c[3])
        : "r"(a[0]), "r"(a[1]), "r"(a[2]), "r"(a[3]), "r"(b0), "r"(b1));
}
#define CP_ASYNC16(dst, src) \
    asm volatile("cp.async.cg.shared.global [%0], [%1], 16;" :: "r"(dst), "l"(src))
#define CP_COMMIT() asm volatile("cp.async.commit_group;" ::: "memory")
#define CP_WAIT0()  asm volatile("cp.async.wait_group 0;" ::: "memory")

// ============================================================================
// sel prob + y=x copy + x->bf16 convert; first blocks also zero g_q / g_cnt.
// ============================================================================
__global__ void sel_copy_kernel(const float* __restrict__ x,
                                const float* __restrict__ sel_w,
                                const float* __restrict__ sel_b,
                                const float* __restrict__ temp,
                                float* __restrict__ y) {
    int r = blockIdx.x;
    int tid = threadIdx.x;
    if (r < 288) {
        int i = r * 256 + tid;
        g_q[i] = 0.f;
        if (i < BATCH) g_cnt[i] = 0;
    }
    const float* xr = x + (size_t)r * DMODEL;
    float* yr = y + (size_t)r * DMODEL;
    __nv_bfloat16* xb = g_xb + (size_t)r * DMODEL;
    float p0 = 0.f, p1 = 0.f;
    #pragma unroll
    for (int j = tid; j < DMODEL; j += 256) {
        float v = xr[j];
        yr[j] = v;
        xb[j] = __float2bfloat16(v);
        float2 w = *(const float2*)&sel_w[2*j];
        p0 = fmaf(v, w.x, p0);
        p1 = fmaf(v, w.y, p1);
    }
    #pragma unroll
    for (int off = 16; off; off >>= 1) {
        p0 += __shfl_down_sync(0xffffffffu, p0, off);
        p1 += __shfl_down_sync(0xffffffffu, p1, off);
    }
    __shared__ float s0[8], s1[8];
    int w = tid >> 5;
    if ((tid & 31) == 0) { s0[w] = p0; s1[w] = p1; }
    __syncthreads();
    if (tid == 0) {
        float a0 = 0.f, a1 = 0.f;
        #pragma unroll
        for (int i = 0; i < 8; i++) { a0 += s0[i]; a1 += s1[i]; }
        a0 += sel_b[0]; a1 += sel_b[1];
        float d = (a1 - a0) / temp[0];
        g_p1[r] = 1.0f / (1.0f + expf(-d));
    }
}

// ============================================================================
// W_kv (cols 768:2304) -> g_wt[n][k] bf16 (transpose)
// ============================================================================
__global__ void w_transpose_kernel(const float* __restrict__ W) {
    __shared__ float t[32][33];
    int n0 = blockIdx.x * 32;
    int k0 = blockIdx.y * 32;
    int tx = threadIdx.x, ty = threadIdx.y;
    #pragma unroll
    for (int i = 0; i < 4; i++)
        t[ty + 8*i][tx] = W[(size_t)(k0 + ty + 8*i) * WQKV_COLS + 768 + n0 + tx];
    __syncthreads();
    #pragma unroll
    for (int i = 0; i < 4; i++)
        g_wt[(size_t)(n0 + ty + 8*i) * DMODEL + k0 + tx] = __float2bfloat16(t[tx][ty + 8*i]);
}

// ============================================================================
// KV GEMM: cp.async 2-stage + swizzled smem (conflict-free ldmatrix) + mma.sync.
// CTA 128x128, 8 warps (2M x 4N), K-chunk 32.  (round-9 proven version)
// SMEM: logical (r, u16B) -> byte (r>>1)*128 + ((((r&1)<<2)|u) ^ ((r>>1)&7))*16
// ============================================================================
#define STAGE_BYTES 8192   // 64 phys rows * 128 B

__global__ void __launch_bounds__(256) kv_mma_kernel(const float* __restrict__ bias) {
    __shared__ __align__(128) __nv_bfloat16 sA[2*4096];
    __shared__ __align__(128) __nv_bfloat16 sB[2*4096];
    int tid = threadIdx.x;
    int wid = tid >> 5, lane = tid & 31;
    int wm = wid & 1, wn = wid >> 1;
    int g = lane >> 2, tg = lane & 3;
    int row0 = blockIdx.y * 128;
    int col0 = blockIdx.x * 128;
    uint32_t baseA = smem_u32(sA), baseB = smem_u32(sB);

    int gr = tid >> 2;
    int gu = tid & 3;
    int par = gr & 1;
    int prow0 = gr >> 1;
    int su = ((par << 2) | gu) ^ (prow0 & 7);
    uint32_t stA = baseA + (uint32_t)(prow0 * 128 + su * 16);
    uint32_t stB = baseB + (uint32_t)(prow0 * 128 + su * 16);
    const __nv_bfloat16* gA0 = g_xb + (size_t)(row0 + gr) * DMODEL + gu * 8;
    const __nv_bfloat16* gA1 = g_xb + (size_t)(row0 + gr + 64) * DMODEL + gu * 8;
    const __nv_bfloat16* gB0 = g_wt + (size_t)(col0 + gr) * DMODEL + gu * 8;
    const __nv_bfloat16* gB1 = g_wt + (size_t)(col0 + gr + 64) * DMODEL + gu * 8;

    int lrow = lane & 15, lsb = lane >> 4;
    int mrA = wm * 64 + lrow;
    int prA = mrA >> 1, paA = (mrA & 1) << 2, xa = prA & 7;
    int nrB = wn * 32 + lrow;
    int prB = nrB >> 1, paB = (nrB & 1) << 2, xb = prB & 7;

    float c[4][4][4];
    #pragma unroll
    for (int mi = 0; mi < 4; mi++)
        #pragma unroll
        for (int ni = 0; ni < 4; ni++)
            #pragma unroll
            for (int j = 0; j < 4; j++) c[mi][ni][j] = 0.f;

    CP_ASYNC16(stA, gA0);                    CP_ASYNC16(stA + 32*128, gA1);
    CP_ASYNC16(stB, gB0);                    CP_ASYNC16(stB + 32*128, gB1);
    CP_COMMIT();

    for (int kc = 0; kc < 24; kc++) {
        CP_WAIT0();
        __syncthreads();
        if (kc < 23) {
            int k0 = (kc + 1) * 32;
            uint32_t so = (uint32_t)(((kc + 1) & 1) * STAGE_BYTES);
            CP_ASYNC16(stA + so, gA0 + k0);          CP_ASYNC16(stA + so + 32*128, gA1 + k0);
            CP_ASYNC16(stB + so, gB0 + k0);          CP_ASYNC16(stB + so + 32*128, gB1 + k0);
            CP_COMMIT();
        }
        uint32_t so = (uint32_t)((kc & 1) * STAGE_BYTES);
        #pragma unroll
        for (int ks = 0; ks < 2; ks++) {
            int u = ks * 2 + lsb;
            uint32_t offA = (uint32_t)(((paA | u) ^ xa) << 4);
            uint32_t offB = (uint32_t)(((paB | u) ^ xb) << 4);
            uint32_t A[4][4], Bf[2][4];
            #pragma unroll
            for (int mi = 0; mi < 4; mi++)
                ldm_x4(A[mi], baseA + so + (uint32_t)((prA + mi*8) * 128) + offA);
            #pragma unroll
            for (int bi = 0; bi < 2; bi++)
                ldm_x4(Bf[bi], baseB + so + (uint32_t)((prB + bi*8) * 128) + offB);
            #pragma unroll
            for (int mi = 0; mi < 4; mi++) {
                mma16816(c[mi][0], A[mi], Bf[0][0], Bf[0][2]);
                mma16816(c[mi][1], A[mi], Bf[0][1], Bf[0][3]);
                mma16816(c[mi][2], A[mi], Bf[1][0], Bf[1][2]);
                mma16816(c[mi][3], A[mi], Bf[1][1], Bf[1][3]);
            }
        }
    }

    #pragma unroll
    for (int mi = 0; mi < 4; mi++) {
        int row = row0 + wm * 64 + mi * 16;
        #pragma unroll
        for (int ni = 0; ni < 4; ni++) {
            int col = col0 + wn * 32 + ni * 8 + 2 * tg;
            float2 bb = *(const float2*)&bias[768 + col];
            float2 r0, r1;
            r0.x = c[mi][ni][0] + bb.x; r0.y = c[mi][ni][1] + bb.y;
            r1.x = c[mi][ni][2] + bb.x; r1.y = c[mi][ni][3] + bb.y;
            *(float2*)&g_kv[(size_t)(row + g) * NKV + col] = r0;
            *(float2*)&g_kv[(size_t)(row + g + 8) * NKV + col] = r1;
        }
    }
}

// ============================================================================
// rank-select top-KSEL: 1 candidate per warp, 8 warps/block, grid (256, 2).
// rank = #{j: p[j] > p[i] || (p[j]==p[i] && j<i)} (jax tie-break).
// ============================================================================
__global__ void __launch_bounds__(256) ranksel_kernel() {
    int b = blockIdx.y;
    __shared__ float vals[SEQL];
    int tid = threadIdx.x;
    int warp = tid >> 5, lane = tid & 31;
    #pragma unroll
    for (int l = 0; l < 8; l++) vals[tid + l * 256] = g_p1[b * SEQL + tid + l * 256];
    __syncthreads();
    int cand = blockIdx.x * 8 + warp;
    float v = vals[cand];
    int cnt = 0;
    #pragma unroll
    for (int l = 0; l < 64; l++) {
        int j = lane + l * 32;
        float u = vals[j];
        cnt += (u > v || (u == v && j < cand)) ? 1 : 0;
    }
    #pragma unroll
    for (int off = 16; off; off >>= 1)
        cnt += __shfl_xor_sync(0xffffffffu, cnt, off);
    if (lane == 0 && cnt < KSEL) {
        int slot = atomicAdd(&g_cnt[b], 1);
        g_idx[b * KSEL + slot] = cand;
    }
}

// ============================================================================
// Q projection: gathered rows from x, k-split (z), atomicAdd into zeroed g_q.
// ============================================================================
__global__ void __launch_bounds__(256) qproj_kernel(const float* __restrict__ x,
                                                    const float* __restrict__ W,
                                                    const float* __restrict__ bias) {
    __shared__ float As[64*48];
    __shared__ float Bs[64*64];
    __shared__ int rowsrc[48];
    int tid = threadIdx.x;
    int tx = tid & 15, ty = tid >> 4;
    int cb = blockIdx.x * 64;
    int rt = blockIdx.y;
    int kb = blockIdx.z * 64;
    if (tid < 48) {
        int r = rt*48 + tid;
        rowsrc[tid] = (r < NQ) ? ((r / KSEL) * SEQL + g_idx[r]) : -1;
    }
    __syncthreads();

    #pragma unroll
    for (int l = 0; l < 3; l++) {
        int fid = tid + l*256;
        int row = fid >> 4;
        int kc  = (fid & 15) << 2;
        int src = rowsrc[row];
        float4 v = make_float4(0.f, 0.f, 0.f, 0.f);
        if (src >= 0) v = *(const float4*)&x[(size_t)src*DMODEL + kb + kc];
        As[(kc+0)*48 + row] = v.x; As[(kc+1)*48 + row] = v.y;
        As[(kc+2)*48 + row] = v.z; As[(kc+3)*48 + row] = v.w;
    }
    #pragma unroll
    for (int l = 0; l < 4; l++) {
        int fid = tid + l*256;
        int kr = fid >> 4;
        int c4 = (fid & 15) << 2;
        *(float4*)&Bs[kr*64 + c4] = *(const float4*)&W[(size_t)(kb + kr)*WQKV_COLS + cb + c4];
    }
    __syncthreads();
    float acc[3][4];
    #pragma unroll
    for (int i = 0; i < 3; i++)
        #pragma unroll
        for (int j = 0; j < 4; j++) acc[i][j] = 0.f;
    #pragma unroll 8
    for (int k = 0; k < 64; k++) {
        float4 bv = *(const float4*)&Bs[k*64 + tx*4];
        #pragma unroll
        for (int i = 0; i < 3; i++) {
            float a = As[k*48 + ty*3 + i];
            acc[i][0] = fmaf(a, bv.x, acc[i][0]);
            acc[i][1] = fmaf(a, bv.y, acc[i][1]);
            acc[i][2] = fmaf(a, bv.z, acc[i][2]);
            acc[i][3] = fmaf(a, bv.w, acc[i][3]);
        }
    }
    #pragma unroll
    for (int i = 0; i < 3; i++) {
        int row = rt*48 + ty*3 + i;
        if (row < NQ) {
            #pragma unroll
            for (int j = 0; j < 4; j++) {
                int col = cb + tx*4 + j;
                float v = acc[i][j] + (blockIdx.z == 0 ? bias[col] : 0.f);
                atomicAdd(&g_q[(size_t)row*DMODEL + col], v);
            }
        }
    }
}

// ============================================================================
// flash-decode attention chunk (fp32)
// ============================================================================
__global__ void __launch_bounds__(256) attn_chunk_kernel() {
    int c  = blockIdx.x;
    int h  = blockIdx.y;
    int b  = blockIdx.z;
    int c0 = c * CH;
    int tid = threadIdx.x;
    int tx = tid & 15, ty = tid >> 4;

    __shared__ float qs[48*HD];
    __shared__ float kv_s[CH*HD];
    __shared__ float S[48*66];
    __shared__ int   ts[48];

    if (tid < 48) ts[tid] = (tid < KSEL) ? g_idx[b*KSEL + tid] : -1;
    for (int idx = tid; idx < 48*HD; idx += 256) {
        int q = idx >> 6, d = idx & 63;
        qs[idx] = (q < KSEL) ? g_q[(size_t)(b*KSEL + q)*DMODEL + h*HD + d] * 0.125f : 0.f;
    }
    const float* kvb = g_kv + (size_t)b * SEQL * NKV;
    #pragma unroll
    for (int l = 0; l < 4; l++) {
        int fid = tid + l*256;
        int key = fid >> 4;
        int dq  = (fid & 15) << 2;
        float4 v = *(const float4*)&kvb[(size_t)(c0 + key)*NKV + h*HD + dq];
        kv_s[(dq+0)*CH + key] = v.x; kv_s[(dq+1)*CH + key] = v.y;
        kv_s[(dq+2)*CH + key] = v.z; kv_s[(dq+3)*CH + key] = v.w;
    }
    __syncthreads();

    float acc[3][4];
    #pragma unroll
    for (int i = 0; i < 3; i++)
        #pragma unroll
        for (int j = 0; j < 4; j++) acc[i][j] = 0.f;
    #pragma unroll 8
    for (int d = 0; d < HD; d++) {
        float4 bv = *(const float4*)&kv_s[d*CH + tx*4];
        #pragma unroll
        for (int i = 0; i < 3; i++) {
            float a = qs[(ty*3+i)*HD + d];
            acc[i][0] = fmaf(a, bv.x, acc[i][0]);
            acc[i][1] = fmaf(a, bv.y, acc[i][1]);
            acc[i][2] = fmaf(a, bv.z, acc[i][2]);
            acc[i][3] = fmaf(a, bv.w, acc[i][3]);
        }
    }
    #pragma unroll
    for (int i = 0; i < 3; i++) {
        int q = ty*3 + i;
        int tq = ts[q];
        #pragma unroll
        for (int j = 0; j < 4; j++) {
            int sg = c0 + tx*4 + j;
            S[q*66 + tx*4 + j] = (q < KSEL && sg <= tq) ? acc[i][j] : -1e30f;
        }
    }
    __syncthreads();

    #pragma unroll
    for (int l = 0; l < 4; l++) {
        int fid = tid + l*256;
        int key = fid >> 4;
        int dq  = (fid & 15) << 2;
        *(float4*)&kv_s[key*HD + dq] =
            *(const float4*)&kvb[(size_t)(c0 + key)*NKV + DMODEL + h*HD + dq];
    }
    if (tid < 48) {
        int q = tid;
        float m = -1e30f;
        #pragma unroll 8
        for (int k = 0; k < CH; k++) m = fmaxf(m, S[q*66 + k]);
        float l = 0.f;
        #pragma unroll 8
        for (int k = 0; k < CH; k++) {
            float v = S[q*66 + k];
            float p = (v > -1e29f) ? __expf(v - m) : 0.f;
            S[q*66 + k] = p;
            l += p;
        }
        int base = ((b*NH + h)*NCH + c)*48 + q;
        g_pm[base] = m;
        g_pl[base] = l;
    }
    __syncthreads();

    float acc2[3][4];
    #pragma unroll
    for (int i = 0; i < 3; i++)
        #pragma unroll
        for (int j = 0; j < 4; j++) acc2[i][j] = 0.f;
    #pragma unroll 8
    for (int k = 0; k < CH; k++) {
        float4 bv = *(const float4*)&kv_s[k*HD + tx*4];
        #pragma unroll
        for (int i = 0; i < 3; i++) {
            float a = S[(ty*3+i)*66 + k];
            acc2[i][0] = fmaf(a, bv.x, acc2[i][0]);
            acc2[i][1] = fmaf(a, bv.y, acc2[i][1]);
            acc2[i][2] = fmaf(a, bv.z, acc2[i][2]);
            acc2[i][3] = fmaf(a, bv.w, acc2[i][3]);
        }
    }
    size_t obase = ((size_t)((b*NH + h)*NCH + c))*48;
    #pragma unroll
    for (int i = 0; i < 3; i++) {
        float4 r; r.x = acc2[i][0]; r.y = acc2[i][1]; r.z = acc2[i][2]; r.w = acc2[i][3];
        *(float4*)&g_po[(obase + ty*3 + i)*HD + tx*4] = r;
    }
}

// ============================================================================
__global__ void attn_combine_kernel() {
    int bx = blockIdx.x;
    int q  = bx / NH;
    int h  = bx % NH;
    int b  = q / KSEL;
    int qi = q % KSEL;
    int d  = threadIdx.x;
    int bh = b*NH + h;

    float m = -1e30f;
    #pragma unroll
    for (int c = 0; c < NCH; c++)
        m = fmaxf(m, g_pm[(bh*NCH + c)*48 + qi]);
    float num = 0.f, den = 0.f;
    #pragma unroll
    for (int c = 0; c < NCH; c++) {
        int base = (bh*NCH + c)*48 + qi;
        float w = __expf(g_pm[base] - m);
        den = fmaf(w, g_pl[base], den);
        num = fmaf(w, g_po[(size_t)base*HD + d], num);
    }
    g_ctx[(size_t)q*DMODEL + h*HD + d] = num / den;
}

// ============================================================================
// out projection: k-split (z), gate, atomicAdd into y
// ============================================================================
__global__ void __launch_bounds__(256) outproj_kernel(const float* __restrict__ W,
                                                      const float* __restrict__ bias,
                                                      float* __restrict__ y) {
    __shared__ float As[64*48];
    __shared__ float Bs[64*64];
    int tid = threadIdx.x;
    int tx = tid & 15, ty = tid >> 4;
    int cb = blockIdx.x * 64;
    int rt = blockIdx.y;
    int kb = blockIdx.z * 64;

    #pragma unroll
    for (int l = 0; l < 3; l++) {
        int fid = tid + l*256;
        int row = fid >> 4;
        int kc  = (fid & 15) << 2;
        float4 v = *(const float4*)&g_ctx[(size_t)(rt*48 + row)*DMODEL + kb + kc];
        As[(kc+0)*48 + row] = v.x; As[(kc+1)*48 + row] = v.y;
        As[(kc+2)*48 + row] = v.z; As[(kc+3)*48 + row] = v.w;
    }
    #pragma unroll
    for (int l = 0; l < 4; l++) {
        int fid = tid + l*256;
        int kr = fid >> 4;
        int c4 = (fid & 15) << 2;
        *(float4*)&Bs[kr*64 + c4] = *(const float4*)&W[(size_t)(kb + kr)*DMODEL + cb + c4];
    }
    __syncthreads();
    float acc[3][4];
    #pragma unroll
    for (int i = 0; i < 3; i++)
        #pragma unroll
        for (int j = 0; j < 4; j++) acc[i][j] = 0.f;
    #pragma unroll 8
    for (int k = 0; k < 64; k++) {
        float4 bv = *(const float4*)&Bs[k*64 + tx*4];
        #pragma unroll
        for (int i = 0; i < 3; i++) {
            float a = As[k*48 + ty*3 + i];
            acc[i][0] = fmaf(a, bv.x, acc[i][0]);
            acc[i][1] = fmaf(a, bv.y, acc[i][1]);
            acc[i][2] = fmaf(a, bv.z, acc[i][2]);
            acc[i][3] = fmaf(a, bv.w, acc[i][3]);
        }
    }
    #pragma unroll
    for (int i = 0; i < 3; i++) {
        int row = rt*48 + ty*3 + i;
        if (row < NQ) {
            int b = row / KSEL;
            int t = g_idx[row];
            float p = g_p1[b*SEQL + t];
            float* yr = y + (size_t)(b*SEQL + t)*DMODEL;
            #pragma unroll
            for (int j = 0; j < 4; j++) {
                int col = cb + tx*4 + j;
                float v = acc[i][j] + (blockIdx.z == 0 ? bias[col] : 0.f);
                atomicAdd(&yr[col], p * v);
            }
        }
    }
}

// ============================================================================
extern "C" void kernel_launch(void* const* d_in, const int* in_sizes, int n_in,
                              void* d_out, int out_size) {
    const float* x     = (const float*)d_in[0];
    const float* Wqkv  = (const float*)d_in[1];
    const float* bqkv  = (const float*)d_in[2];
    const float* sel_w = (const float*)d_in[3];
    const float* sel_b = (const float*)d_in[4];
    const float* out_w = (const float*)d_in[5];
    const float* out_b = (const float*)d_in[6];
    const float* temp  = (const float*)d_in[7];
    float* y = (float*)d_out;

    // fork side stream from the origin (stream 0) — capture-safe pattern
    cudaEventRecord(hx.e0, 0);
    cudaStreamWaitEvent(hx.s2, hx.e0, 0);

    // side stream: W transpose (independent of x)
    w_transpose_kernel<<<dim3(NKV/32, DMODEL/32), dim3(32, 8), 0, hx.s2>>>(Wqkv);

    // main stream: sel/copy/convert (produces g_xb, g_p1, y, zeros g_q/g_cnt)
    sel_copy_kernel<<<NROWS, 256>>>(x, sel_w, sel_b, temp, y);

    // side stream waits for g_xb, then runs the big GEMM
    cudaEventRecord(hx.eX, 0);
    cudaStreamWaitEvent(hx.s2, hx.eX, 0);
    kv_mma_kernel<<<dim3(NKV/128, NROWS/128), 256, 0, hx.s2>>>(bqkv);

    // main stream, overlapped with kv_mma: selection + Q projection
    ranksel_kernel<<<dim3(SEQL/8, BATCH), 256>>>();
    qproj_kernel<<<dim3(12, 2, 12), 256>>>(x, Wqkv, bqkv);

    // join: attention needs g_kv
    cudaEventRecord(hx.eK, hx.s2);
    cudaStreamWaitEvent(0, hx.eK, 0);

    attn_chunk_kernel<<<dim3(NCH, NH, BATCH), 256>>>();
    attn_combine_kernel<<<NQ*NH, HD>>>();
    outproj_kernel<<<dim3(12, 2, 12), 256>>>(out_w, out_b, y);
}

// round 12
// speedup vs baseline: 1.1236x; 1.0581x over previous
#include <cuda_runtime.h>
#include <cuda_bf16.h>
#include <math.h>
#include <stdint.h>

#define BATCH 2
#define SEQL  2048
#define DMODEL 768
#define NH    12
#define HD    64
#define KSEL  46
#define NKV   1536
#define NROWS (BATCH*SEQL)
#define WQKV_COLS 2304
#define NQ    (BATCH*KSEL)
#define NQP   96
#define CH    64
#define NCH   (SEQL/CH)

// -------- scratch --------
__device__ float g_p1[NROWS];
__device__ int   g_idx[NQ];
__device__ int   g_cnt[BATCH];
__device__ float g_kv[(size_t)NROWS * NKV];
__device__ float g_q[NQP*DMODEL];
__device__ float g_ctx[NQP*DMODEL];
__device__ float g_pm[BATCH*NH*NCH*48];
__device__ float g_pl[BATCH*NH*NCH*48];
__device__ float g_po[(size_t)BATCH*NH*NCH*48*HD];
__device__ __nv_bfloat16 g_xb[(size_t)NROWS * DMODEL];   // X bf16 [row][k]
__device__ __nv_bfloat16 g_wt[(size_t)NKV * DMODEL];     // W_kv bf16 [n][k]

// -------- streams/events for capture fork-join (created once at load) ------
struct HxStreams {
    cudaStream_t s2;
    cudaEvent_t e0, eX, eK;
    HxStreams() {
        cudaStreamCreateWithFlags(&s2, cudaStreamNonBlocking);
        cudaEventCreateWithFlags(&e0, cudaEventDisableTiming);
        cudaEventCreateWithFlags(&eX, cudaEventDisableTiming);
        cudaEventCreateWithFlags(&eK, cudaEventDisableTiming);
    }
};
static HxStreams hx;

__device__ __forceinline__ uint32_t smem_u32(const void* p) {
    uint32_t a;
    asm("{ .reg .u64 t; cvta.to.shared.u64 t, %1; cvt.u32.u64 %0, t; }" : "=r"(a) : "l"(p));
    return a;
}
__device__ __forceinline__ void ldm_x4(uint32_t* r, uint32_t addr) {
    asm volatile("ldmatrix.sync.aligned.m8n8.x4.shared.b16 {%0,%1,%2,%3}, [%4];"
        : "=r"(r[0]), "=r"(r[1]), "=r"(r[2]), "=r"(r[3]) : "r"(addr));
}
__device__ __forceinline__ void mma16816(float* c, const uint32_t* a, uint32_t b0, uint32_t b1) {
    asm volatile(
        "mma.sync.aligned.m16n8k16.row.col.f32.bf16.bf16.f32 "
        "{%0,%1,%2,%3}, {%4,%5,%6,%7}, {%8,%9}, {%0,%1,%2,%3};"
        : "+f"(c[0]), "+f"(c[1]), "+f"(c[2]), "+f"(c[3])
        : "r"(a[0]), "r"(a[1]), "r"(a[2]), "r"(a[3]), "r"(b0), "r"(b1));
}
#define CP_ASYNC16(dst, src) \
    asm volatile("cp.async.cg.shared.global [%0], [%1], 16;" :: "r"(dst), "l"(src))
#define CP_COMMIT() asm volatile("cp.async.commit_group;" ::: "memory")
#define CP_WAIT0()  asm volatile("cp.async.wait_group 0;" ::: "memory")

// ============================================================================
// x -> bf16 convert (8 elems/thread); first blocks also zero g_q / g_cnt.
// Grid = NROWS*DMODEL/(8*256) = 1536 blocks.
// ============================================================================
__global__ void x_convert_kernel(const float* __restrict__ X) {
    int blk = blockIdx.x;
    int tid = threadIdx.x;
    if (blk < 288) {
        int i = blk * 256 + tid;
        g_q[i] = 0.f;
        if (i < BATCH) g_cnt[i] = 0;
    }
    size_t i = ((size_t)blk * 256 + tid) * 8;
    float4 a = *(const float4*)(X + i);
    float4 b = *(const float4*)(X + i + 4);
    __nv_bfloat16 o[8];
    o[0]=__float2bfloat16(a.x); o[1]=__float2bfloat16(a.y);
    o[2]=__float2bfloat16(a.z); o[3]=__float2bfloat16(a.w);
    o[4]=__float2bfloat16(b.x); o[5]=__float2bfloat16(b.y);
    o[6]=__float2bfloat16(b.z); o[7]=__float2bfloat16(b.w);
    *(uint4*)(g_xb + i) = *(uint4*)o;
}

// ============================================================================
// sel prob + y = x copy (off the critical path now)
// ============================================================================
__global__ void sel_copy_kernel(const float* __restrict__ x,
                                const float* __restrict__ sel_w,
                                const float* __restrict__ sel_b,
                                const float* __restrict__ temp,
                                float* __restrict__ y) {
    int r = blockIdx.x;
    int tid = threadIdx.x;
    const float* xr = x + (size_t)r * DMODEL;
    float* yr = y + (size_t)r * DMODEL;
    float p0 = 0.f, p1 = 0.f;
    #pragma unroll
    for (int j = tid; j < DMODEL; j += 256) {
        float v = xr[j];
        yr[j] = v;
        float2 w = *(const float2*)&sel_w[2*j];
        p0 = fmaf(v, w.x, p0);
        p1 = fmaf(v, w.y, p1);
    }
    #pragma unroll
    for (int off = 16; off; off >>= 1) {
        p0 += __shfl_down_sync(0xffffffffu, p0, off);
        p1 += __shfl_down_sync(0xffffffffu, p1, off);
    }
    __shared__ float s0[8], s1[8];
    int w = tid >> 5;
    if ((tid & 31) == 0) { s0[w] = p0; s1[w] = p1; }
    __syncthreads();
    if (tid == 0) {
        float a0 = 0.f, a1 = 0.f;
        #pragma unroll
        for (int i = 0; i < 8; i++) { a0 += s0[i]; a1 += s1[i]; }
        a0 += sel_b[0]; a1 += sel_b[1];
        float d = (a1 - a0) / temp[0];
        g_p1[r] = 1.0f / (1.0f + expf(-d));
    }
}

// ============================================================================
// W_kv (cols 768:2304) -> g_wt[n][k] bf16 (transpose)
// ============================================================================
__global__ void w_transpose_kernel(const float* __restrict__ W) {
    __shared__ float t[32][33];
    int n0 = blockIdx.x * 32;
    int k0 = blockIdx.y * 32;
    int tx = threadIdx.x, ty = threadIdx.y;
    #pragma unroll
    for (int i = 0; i < 4; i++)
        t[ty + 8*i][tx] = W[(size_t)(k0 + ty + 8*i) * WQKV_COLS + 768 + n0 + tx];
    __syncthreads();
    #pragma unroll
    for (int i = 0; i < 4; i++)
        g_wt[(size_t)(n0 + ty + 8*i) * DMODEL + k0 + tx] = __float2bfloat16(t[tx][ty + 8*i]);
}

// ============================================================================
// KV GEMM: cp.async 2-stage + swizzled smem (conflict-free ldmatrix) + mma.sync.
// CTA 128x128, 8 warps (2M x 4N), K-chunk 32.  (round-9 proven version)
// SMEM: logical (r, u16B) -> byte (r>>1)*128 + ((((r&1)<<2)|u) ^ ((r>>1)&7))*16
// ============================================================================
#define STAGE_BYTES 8192   // 64 phys rows * 128 B

__global__ void __launch_bounds__(256) kv_mma_kernel(const float* __restrict__ bias) {
    __shared__ __align__(128) __nv_bfloat16 sA[2*4096];
    __shared__ __align__(128) __nv_bfloat16 sB[2*4096];
    int tid = threadIdx.x;
    int wid = tid >> 5, lane = tid & 31;
    int wm = wid & 1, wn = wid >> 1;
    int g = lane >> 2, tg = lane & 3;
    int row0 = blockIdx.y * 128;
    int col0 = blockIdx.x * 128;
    uint32_t baseA = smem_u32(sA), baseB = smem_u32(sB);

    int gr = tid >> 2;
    int gu = tid & 3;
    int par = gr & 1;
    int prow0 = gr >> 1;
    int su = ((par << 2) | gu) ^ (prow0 & 7);
    uint32_t stA = baseA + (uint32_t)(prow0 * 128 + su * 16);
    uint32_t stB = baseB + (uint32_t)(prow0 * 128 + su * 16);
    const __nv_bfloat16* gA0 = g_xb + (size_t)(row0 + gr) * DMODEL + gu * 8;
    const __nv_bfloat16* gA1 = g_xb + (size_t)(row0 + gr + 64) * DMODEL + gu * 8;
    const __nv_bfloat16* gB0 = g_wt + (size_t)(col0 + gr) * DMODEL + gu * 8;
    const __nv_bfloat16* gB1 = g_wt + (size_t)(col0 + gr + 64) * DMODEL + gu * 8;

    int lrow = lane & 15, lsb = lane >> 4;
    int mrA = wm * 64 + lrow;
    int prA = mrA >> 1, paA = (mrA & 1) << 2, xa = prA & 7;
    int nrB = wn * 32 + lrow;
    int prB = nrB >> 1, paB = (nrB & 1) << 2, xb = prB & 7;

    float c[4][4][4];
    #pragma unroll
    for (int mi = 0; mi < 4; mi++)
        #pragma unroll
        for (int ni = 0; ni < 4; ni++)
            #pragma unroll
            for (int j = 0; j < 4; j++) c[mi][ni][j] = 0.f;

    CP_ASYNC16(stA, gA0);                    CP_ASYNC16(stA + 32*128, gA1);
    CP_ASYNC16(stB, gB0);                    CP_ASYNC16(stB + 32*128, gB1);
    CP_COMMIT();

    for (int kc = 0; kc < 24; kc++) {
        CP_WAIT0();
        __syncthreads();
        if (kc < 23) {
            int k0 = (kc + 1) * 32;
            uint32_t so = (uint32_t)(((kc + 1) & 1) * STAGE_BYTES);
            CP_ASYNC16(stA + so, gA0 + k0);          CP_ASYNC16(stA + so + 32*128, gA1 + k0);
            CP_ASYNC16(stB + so, gB0 + k0);          CP_ASYNC16(stB + so + 32*128, gB1 + k0);
            CP_COMMIT();
        }
        uint32_t so = (uint32_t)((kc & 1) * STAGE_BYTES);
        #pragma unroll
        for (int ks = 0; ks < 2; ks++) {
            int u = ks * 2 + lsb;
            uint32_t offA = (uint32_t)(((paA | u) ^ xa) << 4);
            uint32_t offB = (uint32_t)(((paB | u) ^ xb) << 4);
            uint32_t A[4][4], Bf[2][4];
            #pragma unroll
            for (int mi = 0; mi < 4; mi++)
                ldm_x4(A[mi], baseA + so + (uint32_t)((prA + mi*8) * 128) + offA);
            #pragma unroll
            for (int bi = 0; bi < 2; bi++)
                ldm_x4(Bf[bi], baseB + so + (uint32_t)((prB + bi*8) * 128) + offB);
            #pragma unroll
            for (int mi = 0; mi < 4; mi++) {
                mma16816(c[mi][0], A[mi], Bf[0][0], Bf[0][2]);
                mma16816(c[mi][1], A[mi], Bf[0][1], Bf[0][3]);
                mma16816(c[mi][2], A[mi], Bf[1][0], Bf[1][2]);
                mma16816(c[mi][3], A[mi], Bf[1][1], Bf[1][3]);
            }
        }
    }

    #pragma unroll
    for (int mi = 0; mi < 4; mi++) {
        int row = row0 + wm * 64 + mi * 16;
        #pragma unroll
        for (int ni = 0; ni < 4; ni++) {
            int col = col0 + wn * 32 + ni * 8 + 2 * tg;
            float2 bb = *(const float2*)&bias[768 + col];
            float2 r0, r1;
            r0.x = c[mi][ni][0] + bb.x; r0.y = c[mi][ni][1] + bb.y;
            r1.x = c[mi][ni][2] + bb.x; r1.y = c[mi][ni][3] + bb.y;
            *(float2*)&g_kv[(size_t)(row + g) * NKV + col] = r0;
            *(float2*)&g_kv[(size_t)(row + g + 8) * NKV + col] = r1;
        }
    }
}

// ============================================================================
// rank-select top-KSEL: 1 candidate per warp, 8 warps/block, grid (256, 2).
// ============================================================================
__global__ void __launch_bounds__(256) ranksel_kernel() {
    int b = blockIdx.y;
    __shared__ float vals[SEQL];
    int tid = threadIdx.x;
    int warp = tid >> 5, lane = tid & 31;
    #pragma unroll
    for (int l = 0; l < 8; l++) vals[tid + l * 256] = g_p1[b * SEQL + tid + l * 256];
    __syncthreads();
    int cand = blockIdx.x * 8 + warp;
    float v = vals[cand];
    int cnt = 0;
    #pragma unroll
    for (int l = 0; l < 64; l++) {
        int j = lane + l * 32;
        float u = vals[j];
        cnt += (u > v || (u == v && j < cand)) ? 1 : 0;
    }
    #pragma unroll
    for (int off = 16; off; off >>= 1)
        cnt += __shfl_xor_sync(0xffffffffu, cnt, off);
    if (lane == 0 && cnt < KSEL) {
        int slot = atomicAdd(&g_cnt[b], 1);
        g_idx[b * KSEL + slot] = cand;
    }
}

// ============================================================================
// Q projection: gathered rows from x, k-split (z), atomicAdd into zeroed g_q.
// ============================================================================
__global__ void __launch_bounds__(256) qproj_kernel(const float* __restrict__ x,
                                                    const float* __restrict__ W,
                                                    const float* __restrict__ bias) {
    __shared__ float As[64*48];
    __shared__ float Bs[64*64];
    __shared__ int rowsrc[48];
    int tid = threadIdx.x;
    int tx = tid & 15, ty = tid >> 4;
    int cb = blockIdx.x * 64;
    int rt = blockIdx.y;
    int kb = blockIdx.z * 64;
    if (tid < 48) {
        int r = rt*48 + tid;
        rowsrc[tid] = (r < NQ) ? ((r / KSEL) * SEQL + g_idx[r]) : -1;
    }
    __syncthreads();

    #pragma unroll
    for (int l = 0; l < 3; l++) {
        int fid = tid + l*256;
        int row = fid >> 4;
        int kc  = (fid & 15) << 2;
        int src = rowsrc[row];
        float4 v = make_float4(0.f, 0.f, 0.f, 0.f);
        if (src >= 0) v = *(const float4*)&x[(size_t)src*DMODEL + kb + kc];
        As[(kc+0)*48 + row] = v.x; As[(kc+1)*48 + row] = v.y;
        As[(kc+2)*48 + row] = v.z; As[(kc+3)*48 + row] = v.w;
    }
    #pragma unroll
    for (int l = 0; l < 4; l++) {
        int fid = tid + l*256;
        int kr = fid >> 4;
        int c4 = (fid & 15) << 2;
        *(float4*)&Bs[kr*64 + c4] = *(const float4*)&W[(size_t)(kb + kr)*WQKV_COLS + cb + c4];
    }
    __syncthreads();
    float acc[3][4];
    #pragma unroll
    for (int i = 0; i < 3; i++)
        #pragma unroll
        for (int j = 0; j < 4; j++) acc[i][j] = 0.f;
    #pragma unroll 8
    for (int k = 0; k < 64; k++) {
        float4 bv = *(const float4*)&Bs[k*64 + tx*4];
        #pragma unroll
        for (int i = 0; i < 3; i++) {
            float a = As[k*48 + ty*3 + i];
            acc[i][0] = fmaf(a, bv.x, acc[i][0]);
            acc[i][1] = fmaf(a, bv.y, acc[i][1]);
            acc[i][2] = fmaf(a, bv.z, acc[i][2]);
            acc[i][3] = fmaf(a, bv.w, acc[i][3]);
        }
    }
    #pragma unroll
    for (int i = 0; i < 3; i++) {
        int row = rt*48 + ty*3 + i;
        if (row < NQ) {
            #pragma unroll
            for (int j = 0; j < 4; j++) {
                int col = cb + tx*4 + j;
                float v = acc[i][j] + (blockIdx.z == 0 ? bias[col] : 0.f);
                atomicAdd(&g_q[(size_t)row*DMODEL + col], v);
            }
        }
    }
}

// ============================================================================
// flash-decode attention chunk (fp32)
// ============================================================================
__global__ void __launch_bounds__(256) attn_chunk_kernel() {
    int c  = blockIdx.x;
    int h  = blockIdx.y;
    int b  = blockIdx.z;
    int c0 = c * CH;
    int tid = threadIdx.x;
    int tx = tid & 15, ty = tid >> 4;

    __shared__ float qs[48*HD];
    __shared__ float kv_s[CH*HD];
    __shared__ float S[48*66];
    __shared__ int   ts[48];

    if (tid < 48) ts[tid] = (tid < KSEL) ? g_idx[b*KSEL + tid] : -1;
    for (int idx = tid; idx < 48*HD; idx += 256) {
        int q = idx >> 6, d = idx & 63;
        qs[idx] = (q < KSEL) ? g_q[(size_t)(b*KSEL + q)*DMODEL + h*HD + d] * 0.125f : 0.f;
    }
    const float* kvb = g_kv + (size_t)b * SEQL * NKV;
    #pragma unroll
    for (int l = 0; l < 4; l++) {
        int fid = tid + l*256;
        int key = fid >> 4;
        int dq  = (fid & 15) << 2;
        float4 v = *(const float4*)&kvb[(size_t)(c0 + key)*NKV + h*HD + dq];
        kv_s[(dq+0)*CH + key] = v.x; kv_s[(dq+1)*CH + key] = v.y;
        kv_s[(dq+2)*CH + key] = v.z; kv_s[(dq+3)*CH + key] = v.w;
    }
    __syncthreads();

    float acc[3][4];
    #pragma unroll
    for (int i = 0; i < 3; i++)
        #pragma unroll
        for (int j = 0; j < 4; j++) acc[i][j] = 0.f;
    #pragma unroll 8
    for (int d = 0; d < HD; d++) {
        float4 bv = *(const float4*)&kv_s[d*CH + tx*4];
        #pragma unroll
        for (int i = 0; i < 3; i++) {
            float a = qs[(ty*3+i)*HD + d];
            acc[i][0] = fmaf(a, bv.x, acc[i][0]);
            acc[i][1] = fmaf(a, bv.y, acc[i][1]);
            acc[i][2] = fmaf(a, bv.z, acc[i][2]);
            acc[i][3] = fmaf(a, bv.w, acc[i][3]);
        }
    }
    #pragma unroll
    for (int i = 0; i < 3; i++) {
        int q = ty*3 + i;
        int tq = ts[q];
        #pragma unroll
        for (int j = 0; j < 4; j++) {
            int sg = c0 + tx*4 + j;
            S[q*66 + tx*4 + j] = (q < KSEL && sg <= tq) ? acc[i][j] : -1e30f;
        }
    }
    __syncthreads();

    #pragma unroll
    for (int l = 0; l < 4; l++) {
        int fid = tid + l*256;
        int key = fid >> 4;
        int dq  = (fid & 15) << 2;
        *(float4*)&kv_s[key*HD + dq] =
            *(const float4*)&kvb[(size_t)(c0 + key)*NKV + DMODEL + h*HD + dq];
    }
    if (tid < 48) {
        int q = tid;
        float m = -1e30f;
        #pragma unroll 8
        for (int k = 0; k < CH; k++) m = fmaxf(m, S[q*66 + k]);
        float l = 0.f;
        #pragma unroll 8
        for (int k = 0; k < CH; k++) {
            float v = S[q*66 + k];
            float p = (v > -1e29f) ? __expf(v - m) : 0.f;
            S[q*66 + k] = p;
            l += p;
        }
        int base = ((b*NH + h)*NCH + c)*48 + q;
        g_pm[base] = m;
        g_pl[base] = l;
    }
    __syncthreads();

    float acc2[3][4];
    #pragma unroll
    for (int i = 0; i < 3; i++)
        #pragma unroll
        for (int j = 0; j < 4; j++) acc2[i][j] = 0.f;
    #pragma unroll 8
    for (int k = 0; k < CH; k++) {
        float4 bv = *(const float4*)&kv_s[k*HD + tx*4];
        #pragma unroll
        for (int i = 0; i < 3; i++) {
            float a = S[(ty*3+i)*66 + k];
            acc2[i][0] = fmaf(a, bv.x, acc2[i][0]);
            acc2[i][1] = fmaf(a, bv.y, acc2[i][1]);
            acc2[i][2] = fmaf(a, bv.z, acc2[i][2]);
            acc2[i][3] = fmaf(a, bv.w, acc2[i][3]);
        }
    }
    size_t obase = ((size_t)((b*NH + h)*NCH + c))*48;
    #pragma unroll
    for (int i = 0; i < 3; i++) {
        float4 r; r.x = acc2[i][0]; r.y = acc2[i][1]; r.z = acc2[i][2]; r.w = acc2[i][3];
        *(float4*)&g_po[(obase + ty*3 + i)*HD + tx*4] = r;
    }
}

// ============================================================================
__global__ void attn_combine_kernel() {
    int bx = blockIdx.x;
    int q  = bx / NH;
    int h  = bx % NH;
    int b  = q / KSEL;
    int qi = q % KSEL;
    int d  = threadIdx.x;
    int bh = b*NH + h;

    float m = -1e30f;
    #pragma unroll
    for (int c = 0; c < NCH; c++)
        m = fmaxf(m, g_pm[(bh*NCH + c)*48 + qi]);
    float num = 0.f, den = 0.f;
    #pragma unroll
    for (int c = 0; c < NCH; c++) {
        int base = (bh*NCH + c)*48 + qi;
        float w = __expf(g_pm[base] - m);
        den = fmaf(w, g_pl[base], den);
        num = fmaf(w, g_po[(size_t)base*HD + d], num);
    }
    g_ctx[(size_t)q*DMODEL + h*HD + d] = num / den;
}

// ============================================================================
// out projection: k-split (z), gate, atomicAdd into y
// ============================================================================
__global__ void __launch_bounds__(256) outproj_kernel(const float* __restrict__ W,
                                                      const float* __restrict__ bias,
                                                      float* __restrict__ y) {
    __shared__ float As[64*48];
    __shared__ float Bs[64*64];
    int tid = threadIdx.x;
    int tx = tid & 15, ty = tid >> 4;
    int cb = blockIdx.x * 64;
    int rt = blockIdx.y;
    int kb = blockIdx.z * 64;

    #pragma unroll
    for (int l = 0; l < 3; l++) {
        int fid = tid + l*256;
        int row = fid >> 4;
        int kc  = (fid & 15) << 2;
        float4 v = *(const float4*)&g_ctx[(size_t)(rt*48 + row)*DMODEL + kb + kc];
        As[(kc+0)*48 + row] = v.x; As[(kc+1)*48 + row] = v.y;
        As[(kc+2)*48 + row] = v.z; As[(kc+3)*48 + row] = v.w;
    }
    #pragma unroll
    for (int l = 0; l < 4; l++) {
        int fid = tid + l*256;
        int kr = fid >> 4;
        int c4 = (fid & 15) << 2;
        *(float4*)&Bs[kr*64 + c4] = *(const float4*)&W[(size_t)(kb + kr)*DMODEL + cb + c4];
    }
    __syncthreads();
    float acc[3][4];
    #pragma unroll
    for (int i = 0; i < 3; i++)
        #pragma unroll
        for (int j = 0; j < 4; j++) acc[i][j] = 0.f;
    #pragma unroll 8
    for (int k = 0; k < 64; k++) {
        float4 bv = *(const float4*)&Bs[k*64 + tx*4];
        #pragma unroll
        for (int i = 0; i < 3; i++) {
            float a = As[k*48 + ty*3 + i];
            acc[i][0] = fmaf(a, bv.x, acc[i][0]);
            acc[i][1] = fmaf(a, bv.y, acc[i][1]);
            acc[i][2] = fmaf(a, bv.z, acc[i][2]);
            acc[i][3] = fmaf(a, bv.w, acc[i][3]);
        }
    }
    #pragma unroll
    for (int i = 0; i < 3; i++) {
        int row = rt*48 + ty*3 + i;
        if (row < NQ) {
            int b = row / KSEL;
            int t = g_idx[row];
            float p = g_p1[b*SEQL + t];
            float* yr = y + (size_t)(b*SEQL + t)*DMODEL;
            #pragma unroll
            for (int j = 0; j < 4; j++) {
                int col = cb + tx*4 + j;
                float v = acc[i][j] + (blockIdx.z == 0 ? bias[col] : 0.f);
                atomicAdd(&yr[col], p * v);
            }
        }
    }
}

// ============================================================================
extern "C" void kernel_launch(void* const* d_in, const int* in_sizes, int n_in,
                              void* d_out, int out_size) {
    const float* x     = (const float*)d_in[0];
    const float* Wqkv  = (const float*)d_in[1];
    const float* bqkv  = (const float*)d_in[2];
    const float* sel_w = (const float*)d_in[3];
    const float* sel_b = (const float*)d_in[4];
    const float* out_w = (const float*)d_in[5];
    const float* out_b = (const float*)d_in[6];
    const float* temp  = (const float*)d_in[7];
    float* y = (float*)d_out;

    // fork side stream from the origin — capture-safe pattern
    cudaEventRecord(hx.e0, 0);
    cudaStreamWaitEvent(hx.s2, hx.e0, 0);

    // side stream: W transpose (independent of x)
    w_transpose_kernel<<<dim3(NKV/32, DMODEL/32), dim3(32, 8), 0, hx.s2>>>(Wqkv);

    // main stream: x -> bf16 (fast; this alone gates kv_mma)
    x_convert_kernel<<<NROWS*DMODEL/(8*256), 256>>>(x);
    cudaEventRecord(hx.eX, 0);
    cudaStreamWaitEvent(hx.s2, hx.eX, 0);

    // side stream: big GEMM
    kv_mma_kernel<<<dim3(NKV/128, NROWS/128), 256, 0, hx.s2>>>(bqkv);

    // main stream, overlapped with kv_mma: y copy + selection + Q projection
    sel_copy_kernel<<<NROWS, 256>>>(x, sel_w, sel_b, temp, y);
    ranksel_kernel<<<dim3(SEQL/8, BATCH), 256>>>();
    qproj_kernel<<<dim3(12, 2, 12), 256>>>(x, Wqkv, bqkv);

    // join: attention needs g_kv
    cudaEventRecord(hx.eK, hx.s2);
    cudaStreamWaitEvent(0, hx.eK, 0);

    attn_chunk_kernel<<<dim3(NCH, NH, BATCH), 256>>>();
    attn_combine_kernel<<<NQ*NH, HD>>>();
    outproj_kernel<<<dim3(12, 2, 12), 256>>>(out_w, out_b, y);
}

// round 13
// speedup vs baseline: 1.2737x; 1.1335x over previous
#include <cuda_runtime.h>
#include <cuda_bf16.h>
#include <math.h>
#include <stdint.h>

#define BATCH 2
#define SEQL  2048
#define DMODEL 768
#define NH    12
#define HD    64
#define KSEL  46
#define NKV   1536
#define NROWS (BATCH*SEQL)
#define WQKV_COLS 2304
#define NQ    (BATCH*KSEL)
#define NQP   96
#define CH    64
#define NCH   (SEQL/CH)

// -------- scratch --------
__device__ float g_p1[NROWS];
__device__ int   g_idx[NQ];
__device__ int   g_cnt[BATCH];
__device__ float g_q[NQP*DMODEL];
__device__ float g_ctx[NQP*DMODEL];
__device__ float g_pm[BATCH*NH*NCH*48];
__device__ float g_pl[BATCH*NH*NCH*48];
__device__ float g_po[(size_t)BATCH*NH*NCH*48*HD];
__device__ __nv_bfloat16 g_xb[(size_t)NROWS * DMODEL];    // X bf16 [row][k]
__device__ __nv_bfloat16 g_wt[(size_t)NKV * DMODEL];      // W_kv bf16 [n][k]
__device__ __nv_bfloat16 g_kvb[(size_t)NROWS * NKV];      // K|V bf16 [row][0:768|768:1536]

// -------- streams/events for capture fork-join (created once at load) ------
struct HxStreams {
    cudaStream_t s2;
    cudaEvent_t e0, eX, eK;
    HxStreams() {
        cudaStreamCreateWithFlags(&s2, cudaStreamNonBlocking);
        cudaEventCreateWithFlags(&e0, cudaEventDisableTiming);
        cudaEventCreateWithFlags(&eX, cudaEventDisableTiming);
        cudaEventCreateWithFlags(&eK, cudaEventDisableTiming);
    }
};
static HxStreams hx;

__device__ __forceinline__ uint32_t smem_u32(const void* p) {
    uint32_t a;
    asm("{ .reg .u64 t; cvta.to.shared.u64 t, %1; cvt.u32.u64 %0, t; }" : "=r"(a) : "l"(p));
    return a;
}
__device__ __forceinline__ void ldm_x4(uint32_t* r, uint32_t addr) {
    asm volatile("ldmatrix.sync.aligned.m8n8.x4.shared.b16 {%0,%1,%2,%3}, [%4];"
        : "=r"(r[0]), "=r"(r[1]), "=r"(r[2]), "=r"(r[3]) : "r"(addr));
}
__device__ __forceinline__ void mma16816(float* c, const uint32_t* a, uint32_t b0, uint32_t b1) {
    asm volatile(
        "mma.sync.aligned.m16n8k16.row.col.f32.bf16.bf16.f32 "
        "{%0,%1,%2,%3}, {%4,%5,%6,%7}, {%8,%9}, {%0,%1,%2,%3};"
        : "+f"(c[0]), "+f"(c[1]), "+f"(c[2]), "+f"(c[3])
        : "r"(a[0]), "r"(a[1]), "r"(a[2]), "r"(a[3]), "r"(b0), "r"(b1));
}
#define CP_ASYNC16(dst, src) \
    asm volatile("cp.async.cg.shared.global [%0], [%1], 16;" :: "r"(dst), "l"(src))
#define CP_COMMIT() asm volatile("cp.async.commit_group;" ::: "memory")
#define CP_WAIT0()  asm volatile("cp.async.wait_group 0;" ::: "memory")

// ============================================================================
// x -> bf16 convert; first blocks also zero g_q / g_cnt.
// ============================================================================
__global__ void x_convert_kernel(const float* __restrict__ X) {
    int blk = blockIdx.x;
    int tid = threadIdx.x;
    if (blk < 288) {
        int i = blk * 256 + tid;
        g_q[i] = 0.f;
        if (i < BATCH) g_cnt[i] = 0;
    }
    size_t i = ((size_t)blk * 256 + tid) * 8;
    float4 a = *(const float4*)(X + i);
    float4 b = *(const float4*)(X + i + 4);
    __nv_bfloat16 o[8];
    o[0]=__float2bfloat16(a.x); o[1]=__float2bfloat16(a.y);
    o[2]=__float2bfloat16(a.z); o[3]=__float2bfloat16(a.w);
    o[4]=__float2bfloat16(b.x); o[5]=__float2bfloat16(b.y);
    o[6]=__float2bfloat16(b.z); o[7]=__float2bfloat16(b.w);
    *(uint4*)(g_xb + i) = *(uint4*)o;
}

// ============================================================================
// sel prob + y = x copy (off the critical path)
// ============================================================================
__global__ void sel_copy_kernel(const float* __restrict__ x,
                                const float* __restrict__ sel_w,
                                const float* __restrict__ sel_b,
                                const float* __restrict__ temp,
                                float* __restrict__ y) {
    int r = blockIdx.x;
    int tid = threadIdx.x;
    const float* xr = x + (size_t)r * DMODEL;
    float* yr = y + (size_t)r * DMODEL;
    float p0 = 0.f, p1 = 0.f;
    #pragma unroll
    for (int j = tid; j < DMODEL; j += 256) {
        float v = xr[j];
        yr[j] = v;
        float2 w = *(const float2*)&sel_w[2*j];
        p0 = fmaf(v, w.x, p0);
        p1 = fmaf(v, w.y, p1);
    }
    #pragma unroll
    for (int off = 16; off; off >>= 1) {
        p0 += __shfl_down_sync(0xffffffffu, p0, off);
        p1 += __shfl_down_sync(0xffffffffu, p1, off);
    }
    __shared__ float s0[8], s1[8];
    int w = tid >> 5;
    if ((tid & 31) == 0) { s0[w] = p0; s1[w] = p1; }
    __syncthreads();
    if (tid == 0) {
        float a0 = 0.f, a1 = 0.f;
        #pragma unroll
        for (int i = 0; i < 8; i++) { a0 += s0[i]; a1 += s1[i]; }
        a0 += sel_b[0]; a1 += sel_b[1];
        float d = (a1 - a0) / temp[0];
        g_p1[r] = 1.0f / (1.0f + expf(-d));
    }
}

// ============================================================================
// W_kv (cols 768:2304) -> g_wt[n][k] bf16 (transpose)
// ============================================================================
__global__ void w_transpose_kernel(const float* __restrict__ W) {
    __shared__ float t[32][33];
    int n0 = blockIdx.x * 32;
    int k0 = blockIdx.y * 32;
    int tx = threadIdx.x, ty = threadIdx.y;
    #pragma unroll
    for (int i = 0; i < 4; i++)
        t[ty + 8*i][tx] = W[(size_t)(k0 + ty + 8*i) * WQKV_COLS + 768 + n0 + tx];
    __syncthreads();
    #pragma unroll
    for (int i = 0; i < 4; i++)
        g_wt[(size_t)(n0 + ty + 8*i) * DMODEL + k0 + tx] = __float2bfloat16(t[tx][ty + 8*i]);
}

// ============================================================================
// KV GEMM: cp.async 2-stage + swizzled smem + mma.sync. Output bf16 -> g_kvb.
// CTA 128x128, 8 warps (2M x 4N), K-chunk 32.
// ============================================================================
#define STAGE_BYTES 8192

__global__ void __launch_bounds__(256) kv_mma_kernel(const float* __restrict__ bias) {
    __shared__ __align__(128) __nv_bfloat16 sA[2*4096];
    __shared__ __align__(128) __nv_bfloat16 sB[2*4096];
    int tid = threadIdx.x;
    int wid = tid >> 5, lane = tid & 31;
    int wm = wid & 1, wn = wid >> 1;
    int g = lane >> 2, tg = lane & 3;
    int row0 = blockIdx.y * 128;
    int col0 = blockIdx.x * 128;
    uint32_t baseA = smem_u32(sA), baseB = smem_u32(sB);

    int gr = tid >> 2;
    int gu = tid & 3;
    int par = gr & 1;
    int prow0 = gr >> 1;
    int su = ((par << 2) | gu) ^ (prow0 & 7);
    uint32_t stA = baseA + (uint32_t)(prow0 * 128 + su * 16);
    uint32_t stB = baseB + (uint32_t)(prow0 * 128 + su * 16);
    const __nv_bfloat16* gA0 = g_xb + (size_t)(row0 + gr) * DMODEL + gu * 8;
    const __nv_bfloat16* gA1 = g_xb + (size_t)(row0 + gr + 64) * DMODEL + gu * 8;
    const __nv_bfloat16* gB0 = g_wt + (size_t)(col0 + gr) * DMODEL + gu * 8;
    const __nv_bfloat16* gB1 = g_wt + (size_t)(col0 + gr + 64) * DMODEL + gu * 8;

    int lrow = lane & 15, lsb = lane >> 4;
    int mrA = wm * 64 + lrow;
    int prA = mrA >> 1, paA = (mrA & 1) << 2, xa = prA & 7;
    int nrB = wn * 32 + lrow;
    int prB = nrB >> 1, paB = (nrB & 1) << 2, xb = prB & 7;

    float c[4][4][4];
    #pragma unroll
    for (int mi = 0; mi < 4; mi++)
        #pragma unroll
        for (int ni = 0; ni < 4; ni++)
            #pragma unroll
            for (int j = 0; j < 4; j++) c[mi][ni][j] = 0.f;

    CP_ASYNC16(stA, gA0);                    CP_ASYNC16(stA + 32*128, gA1);
    CP_ASYNC16(stB, gB0);                    CP_ASYNC16(stB + 32*128, gB1);
    CP_COMMIT();

    for (int kc = 0; kc < 24; kc++) {
        CP_WAIT0();
        __syncthreads();
        if (kc < 23) {
            int k0 = (kc + 1) * 32;
            uint32_t so = (uint32_t)(((kc + 1) & 1) * STAGE_BYTES);
            CP_ASYNC16(stA + so, gA0 + k0);          CP_ASYNC16(stA + so + 32*128, gA1 + k0);
            CP_ASYNC16(stB + so, gB0 + k0);          CP_ASYNC16(stB + so + 32*128, gB1 + k0);
            CP_COMMIT();
        }
        uint32_t so = (uint32_t)((kc & 1) * STAGE_BYTES);
        #pragma unroll
        for (int ks = 0; ks < 2; ks++) {
            int u = ks * 2 + lsb;
            uint32_t offA = (uint32_t)(((paA | u) ^ xa) << 4);
            uint32_t offB = (uint32_t)(((paB | u) ^ xb) << 4);
            uint32_t A[4][4], Bf[2][4];
            #pragma unroll
            for (int mi = 0; mi < 4; mi++)
                ldm_x4(A[mi], baseA + so + (uint32_t)((prA + mi*8) * 128) + offA);
            #pragma unroll
            for (int bi = 0; bi < 2; bi++)
                ldm_x4(Bf[bi], baseB + so + (uint32_t)((prB + bi*8) * 128) + offB);
            #pragma unroll
            for (int mi = 0; mi < 4; mi++) {
                mma16816(c[mi][0], A[mi], Bf[0][0], Bf[0][2]);
                mma16816(c[mi][1], A[mi], Bf[0][1], Bf[0][3]);
                mma16816(c[mi][2], A[mi], Bf[1][0], Bf[1][2]);
                mma16816(c[mi][3], A[mi], Bf[1][1], Bf[1][3]);
            }
        }
    }

    #pragma unroll
    for (int mi = 0; mi < 4; mi++) {
        int row = row0 + wm * 64 + mi * 16;
        #pragma unroll
        for (int ni = 0; ni < 4; ni++) {
            int col = col0 + wn * 32 + ni * 8 + 2 * tg;
            float2 bb = *(const float2*)&bias[768 + col];
            __nv_bfloat162 r0, r1;
            r0.x = __float2bfloat16(c[mi][ni][0] + bb.x);
            r0.y = __float2bfloat16(c[mi][ni][1] + bb.y);
            r1.x = __float2bfloat16(c[mi][ni][2] + bb.x);
            r1.y = __float2bfloat16(c[mi][ni][3] + bb.y);
            *(__nv_bfloat162*)&g_kvb[(size_t)(row + g) * NKV + col] = r0;
            *(__nv_bfloat162*)&g_kvb[(size_t)(row + g + 8) * NKV + col] = r1;
        }
    }
}

// ============================================================================
// rank-select top-KSEL: 1 candidate per warp, grid (256, 2).
// ============================================================================
__global__ void __launch_bounds__(256) ranksel_kernel() {
    int b = blockIdx.y;
    __shared__ float vals[SEQL];
    int tid = threadIdx.x;
    int warp = tid >> 5, lane = tid & 31;
    #pragma unroll
    for (int l = 0; l < 8; l++) vals[tid + l * 256] = g_p1[b * SEQL + tid + l * 256];
    __syncthreads();
    int cand = blockIdx.x * 8 + warp;
    float v = vals[cand];
    int cnt = 0;
    #pragma unroll
    for (int l = 0; l < 64; l++) {
        int j = lane + l * 32;
        float u = vals[j];
        cnt += (u > v || (u == v && j < cand)) ? 1 : 0;
    }
    #pragma unroll
    for (int off = 16; off; off >>= 1)
        cnt += __shfl_xor_sync(0xffffffffu, cnt, off);
    if (lane == 0 && cnt < KSEL) {
        int slot = atomicAdd(&g_cnt[b], 1);
        g_idx[b * KSEL + slot] = cand;
    }
}

// ============================================================================
// Q projection: gathered rows from x, k-split (z), atomicAdd into zeroed g_q.
// ============================================================================
__global__ void __launch_bounds__(256) qproj_kernel(const float* __restrict__ x,
                                                    const float* __restrict__ W,
                                                    const float* __restrict__ bias) {
    __shared__ float As[64*48];
    __shared__ float Bs[64*64];
    __shared__ int rowsrc[48];
    int tid = threadIdx.x;
    int tx = tid & 15, ty = tid >> 4;
    int cb = blockIdx.x * 64;
    int rt = blockIdx.y;
    int kb = blockIdx.z * 64;
    if (tid < 48) {
        int r = rt*48 + tid;
        rowsrc[tid] = (r < NQ) ? ((r / KSEL) * SEQL + g_idx[r]) : -1;
    }
    __syncthreads();

    #pragma unroll
    for (int l = 0; l < 3; l++) {
        int fid = tid + l*256;
        int row = fid >> 4;
        int kc  = (fid & 15) << 2;
        int src = rowsrc[row];
        float4 v = make_float4(0.f, 0.f, 0.f, 0.f);
        if (src >= 0) v = *(const float4*)&x[(size_t)src*DMODEL + kb + kc];
        As[(kc+0)*48 + row] = v.x; As[(kc+1)*48 + row] = v.y;
        As[(kc+2)*48 + row] = v.z; As[(kc+3)*48 + row] = v.w;
    }
    #pragma unroll
    for (int l = 0; l < 4; l++) {
        int fid = tid + l*256;
        int kr = fid >> 4;
        int c4 = (fid & 15) << 2;
        *(float4*)&Bs[kr*64 + c4] = *(const float4*)&W[(size_t)(kb + kr)*WQKV_COLS + cb + c4];
    }
    __syncthreads();
    float acc[3][4];
    #pragma unroll
    for (int i = 0; i < 3; i++)
        #pragma unroll
        for (int j = 0; j < 4; j++) acc[i][j] = 0.f;
    #pragma unroll 8
    for (int k = 0; k < 64; k++) {
        float4 bv = *(const float4*)&Bs[k*64 + tx*4];
        #pragma unroll
        for (int i = 0; i < 3; i++) {
            float a = As[k*48 + ty*3 + i];
            acc[i][0] = fmaf(a, bv.x, acc[i][0]);
            acc[i][1] = fmaf(a, bv.y, acc[i][1]);
            acc[i][2] = fmaf(a, bv.z, acc[i][2]);
            acc[i][3] = fmaf(a, bv.w, acc[i][3]);
        }
    }
    #pragma unroll
    for (int i = 0; i < 3; i++) {
        int row = rt*48 + ty*3 + i;
        if (row < NQ) {
            #pragma unroll
            for (int j = 0; j < 4; j++) {
                int col = cb + tx*4 + j;
                float v = acc[i][j] + (blockIdx.z == 0 ? bias[col] : 0.f);
                atomicAdd(&g_q[(size_t)row*DMODEL + col], v);
            }
        }
    }
}

// ============================================================================
// flash-decode attention chunk via mma.sync (bf16 Q/K/V/P, fp32 softmax).
// Block = (chunk, head, batch), 256 threads, 8 warps (4M x 2N), Q padded to 64.
// SMEM swizzle: byte(row, u16B) = row*128 + ((u ^ (row&7))<<4)
// ============================================================================
__global__ void __launch_bounds__(256) attn_chunk_kernel() {
    int c  = blockIdx.x;
    int h  = blockIdx.y;
    int b  = blockIdx.z;
    int c0 = c * CH;
    int tid = threadIdx.x;
    int wid = tid >> 5, lane = tid & 31;
    int wm = wid & 3, wn = wid >> 2;
    int g = lane >> 2, tg = lane & 3;
    int lrow = lane & 15, lsb = lane >> 4;

    __shared__ __align__(128) __nv_bfloat16 Qs[64*64];   // Q, later P (bf16)
    __shared__ __align__(128) __nv_bfloat16 Ks[64*64];   // K, later V^T (bf16)
    __shared__ float Ss[64*66];
    __shared__ int   ts[64];

    if (tid < 64) ts[tid] = (tid < KSEL) ? g_idx[b*KSEL + tid] : -1;

    // stage Q (scaled, bf16, swizzled); rows >= KSEL zero
    for (int idx = tid; idx < 64*64; idx += 256) {
        int q = idx >> 6, d = idx & 63;
        float v = (q < KSEL) ? g_q[(size_t)(b*KSEL + q)*DMODEL + h*HD + d] * 0.125f : 0.f;
        *(__nv_bfloat16*)((char*)Qs + q*128 + ((((d>>3)) ^ (q&7))<<4) + (d&7)*2) =
            __float2bfloat16(v);
    }
    // stage K (bf16, swizzled): 64 keys x 8 units of 16B
    const __nv_bfloat16* kvb = g_kvb + (size_t)b * SEQL * NKV;
    #pragma unroll
    for (int l = 0; l < 2; l++) {
        int fid = tid + l*256;
        int key = fid >> 3, u = fid & 7;
        uint4 v = *(const uint4*)(kvb + (size_t)(c0 + key)*NKV + h*HD + u*8);
        *(uint4*)((char*)Ks + key*128 + ((u ^ (key&7))<<4)) = v;
    }
    __syncthreads();

    uint32_t qBase = smem_u32(Qs), kBase = smem_u32(Ks);
    int arow = wm*16 + lrow;
    int brow = wn*32 + lrow;
    uint32_t aOffR = (uint32_t)(arow*128);
    uint32_t b0R = (uint32_t)(brow*128);
    uint32_t b1R = (uint32_t)((brow+16)*128);
    int axa = arow & 7, bx0 = brow & 7, bx1 = (brow+16) & 7;

    // S = Q @ K^T (M=64 padded, N=64, K=64)
    float sc[4][4];
    #pragma unroll
    for (int ni = 0; ni < 4; ni++)
        #pragma unroll
        for (int j = 0; j < 4; j++) sc[ni][j] = 0.f;
    #pragma unroll
    for (int ks = 0; ks < 4; ks++) {
        int u = ks*2 + lsb;
        uint32_t A[4], B0[4], B1[4];
        ldm_x4(A,  qBase + aOffR + (uint32_t)(((u ^ axa))<<4));
        ldm_x4(B0, kBase + b0R   + (uint32_t)(((u ^ bx0))<<4));
        ldm_x4(B1, kBase + b1R   + (uint32_t)(((u ^ bx1))<<4));
        mma16816(sc[0], A, B0[0], B0[2]);
        mma16816(sc[1], A, B0[1], B0[3]);
        mma16816(sc[2], A, B1[0], B1[2]);
        mma16816(sc[3], A, B1[1], B1[3]);
    }
    // write masked S
    #pragma unroll
    for (int ni = 0; ni < 4; ni++) {
        int col = wn*32 + ni*8 + 2*tg;
        int sg = c0 + col;
        int q0 = wm*16 + g, q1 = q0 + 8;
        int t0 = ts[q0], t1 = ts[q1];
        Ss[q0*66 + col]     = (q0 < KSEL && sg     <= t0) ? sc[ni][0] : -1e30f;
        Ss[q0*66 + col + 1] = (q0 < KSEL && sg + 1 <= t0) ? sc[ni][1] : -1e30f;
        Ss[q1*66 + col]     = (q1 < KSEL && sg     <= t1) ? sc[ni][2] : -1e30f;
        Ss[q1*66 + col + 1] = (q1 < KSEL && sg + 1 <= t1) ? sc[ni][3] : -1e30f;
    }
    __syncthreads();

    // stage V transposed into Ks: Vt[d][key] (bf16, swizzled)
    #pragma unroll
    for (int l = 0; l < 2; l++) {
        int fid = tid + l*256;
        int key = fid >> 3, db = (fid & 7) * 8;
        uint4 v = *(const uint4*)(kvb + (size_t)(c0 + key)*NKV + DMODEL + h*HD + db);
        __nv_bfloat16 e[8];
        *(uint4*)e = v;
        #pragma unroll
        for (int j = 0; j < 8; j++) {
            int d = db + j;
            *(__nv_bfloat16*)((char*)Ks + d*128 + ((((key>>3) ^ (d&7)))<<4) + (key&7)*2) = e[j];
        }
    }
    // softmax per row (threads 0..63); store p back into Ss
    if (tid < 64) {
        int q = tid;
        if (q < KSEL) {
            float m = -1e30f;
            #pragma unroll 8
            for (int k = 0; k < CH; k++) m = fmaxf(m, Ss[q*66 + k]);
            float lsum = 0.f;
            #pragma unroll 8
            for (int k = 0; k < CH; k++) {
                float v = Ss[q*66 + k];
                float p = (v > -1e29f) ? __expf(v - m) : 0.f;
                Ss[q*66 + k] = p;
                lsum += p;
            }
            int base = ((b*NH + h)*NCH + c)*48 + q;
            g_pm[base] = m;
            g_pl[base] = lsum;
        } else {
            #pragma unroll 8
            for (int k = 0; k < CH; k++) Ss[q*66 + k] = 0.f;
        }
    }
    __syncthreads();

    // P -> bf16 into Qs (swizzled)
    {
        int q = tid >> 2, kb = (tid & 3) * 16;
        __nv_bfloat16 e[16];
        #pragma unroll
        for (int j = 0; j < 16; j++) e[j] = __float2bfloat16(Ss[q*66 + kb + j]);
        int u0 = kb >> 3;
        *(uint4*)((char*)Qs + q*128 + (((u0    ) ^ (q&7))<<4)) = *(uint4*)e;
        *(uint4*)((char*)Qs + q*128 + (((u0 + 1) ^ (q&7))<<4)) = *(uint4*)(e + 8);
    }
    __syncthreads();

    // O = P @ V  (A = Pb in Qs, B = Vt in Ks)
    float oc[4][4];
    #pragma unroll
    for (int ni = 0; ni < 4; ni++)
        #pragma unroll
        for (int j = 0; j < 4; j++) oc[ni][j] = 0.f;
    #pragma unroll
    for (int ks = 0; ks < 4; ks++) {
        int u = ks*2 + lsb;
        uint32_t A[4], B0[4], B1[4];
        ldm_x4(A,  qBase + aOffR + (uint32_t)(((u ^ axa))<<4));
        ldm_x4(B0, kBase + b0R   + (uint32_t)(((u ^ bx0))<<4));
        ldm_x4(B1, kBase + b1R   + (uint32_t)(((u ^ bx1))<<4));
        mma16816(oc[0], A, B0[0], B0[2]);
        mma16816(oc[1], A, B0[1], B0[3]);
        mma16816(oc[2], A, B1[0], B1[2]);
        mma16816(oc[3], A, B1[1], B1[3]);
    }
    size_t obase = ((size_t)((b*NH + h)*NCH + c))*48;
    #pragma unroll
    for (int ni = 0; ni < 4; ni++) {
        int col = wn*32 + ni*8 + 2*tg;
        int q0 = wm*16 + g, q1 = q0 + 8;
        if (q0 < 48) {
            float2 r; r.x = oc[ni][0]; r.y = oc[ni][1];
            *(float2*)&g_po[(obase + q0)*HD + col] = r;
        }
        if (q1 < 48) {
            float2 r; r.x = oc[ni][2]; r.y = oc[ni][3];
            *(float2*)&g_po[(obase + q1)*HD + col] = r;
        }
    }
}

// ============================================================================
__global__ void attn_combine_kernel() {
    int bx = blockIdx.x;
    int q  = bx / NH;
    int h  = bx % NH;
    int b  = q / KSEL;
    int qi = q % KSEL;
    int d  = threadIdx.x;
    int bh = b*NH + h;

    float m = -1e30f;
    #pragma unroll
    for (int c = 0; c < NCH; c++)
        m = fmaxf(m, g_pm[(bh*NCH + c)*48 + qi]);
    float num = 0.f, den = 0.f;
    #pragma unroll
    for (int c = 0; c < NCH; c++) {
        int base = (bh*NCH + c)*48 + qi;
        float w = __expf(g_pm[base] - m);
        den = fmaf(w, g_pl[base], den);
        num = fmaf(w, g_po[(size_t)base*HD + d], num);
    }
    g_ctx[(size_t)q*DMODEL + h*HD + d] = num / den;
}

// ============================================================================
// out projection: k-split (z), gate, atomicAdd into y
// ============================================================================
__global__ void __launch_bounds__(256) outproj_kernel(const float* __restrict__ W,
                                                      const float* __restrict__ bias,
                                                      float* __restrict__ y) {
    __shared__ float As[64*48];
    __shared__ float Bs[64*64];
    int tid = threadIdx.x;
    int tx = tid & 15, ty = tid >> 4;
    int cb = blockIdx.x * 64;
    int rt = blockIdx.y;
    int kb = blockIdx.z * 64;

    #pragma unroll
    for (int l = 0; l < 3; l++) {
        int fid = tid + l*256;
        int row = fid >> 4;
        int kc  = (fid & 15) << 2;
        float4 v = *(const float4*)&g_ctx[(size_t)(rt*48 + row)*DMODEL + kb + kc];
        As[(kc+0)*48 + row] = v.x; As[(kc+1)*48 + row] = v.y;
        As[(kc+2)*48 + row] = v.z; As[(kc+3)*48 + row] = v.w;
    }
    #pragma unroll
    for (int l = 0; l < 4; l++) {
        int fid = tid + l*256;
        int kr = fid >> 4;
        int c4 = (fid & 15) << 2;
        *(float4*)&Bs[kr*64 + c4] = *(const float4*)&W[(size_t)(kb + kr)*DMODEL + cb + c4];
    }
    __syncthreads();
    float acc[3][4];
    #pragma unroll
    for (int i = 0; i < 3; i++)
        #pragma unroll
        for (int j = 0; j < 4; j++) acc[i][j] = 0.f;
    #pragma unroll 8
    for (int k = 0; k < 64; k++) {
        float4 bv = *(const float4*)&Bs[k*64 + tx*4];
        #pragma unroll
        for (int i = 0; i < 3; i++) {
            float a = As[k*48 + ty*3 + i];
            acc[i][0] = fmaf(a, bv.x, acc[i][0]);
            acc[i][1] = fmaf(a, bv.y, acc[i][1]);
            acc[i][2] = fmaf(a, bv.z, acc[i][2]);
            acc[i][3] = fmaf(a, bv.w, acc[i][3]);
        }
    }
    #pragma unroll
    for (int i = 0; i < 3; i++) {
        int row = rt*48 + ty*3 + i;
        if (row < NQ) {
            int b = row / KSEL;
            int t = g_idx[row];
            float p = g_p1[b*SEQL + t];
            float* yr = y + (size_t)(b*SEQL + t)*DMODEL;
            #pragma unroll
            for (int j = 0; j < 4; j++) {
                int col = cb + tx*4 + j;
                float v = acc[i][j] + (blockIdx.z == 0 ? bias[col] : 0.f);
                atomicAdd(&yr[col], p * v);
            }
        }
    }
}

// ============================================================================
extern "C" void kernel_launch(void* const* d_in, const int* in_sizes, int n_in,
                              void* d_out, int out_size) {
    const float* x     = (const float*)d_in[0];
    const float* Wqkv  = (const float*)d_in[1];
    const float* bqkv  = (const float*)d_in[2];
    const float* sel_w = (const float*)d_in[3];
    const float* sel_b = (const float*)d_in[4];
    const float* out_w = (const float*)d_in[5];
    const float* out_b = (const float*)d_in[6];
    const float* temp  = (const float*)d_in[7];
    float* y = (float*)d_out;

    cudaEventRecord(hx.e0, 0);
    cudaStreamWaitEvent(hx.s2, hx.e0, 0);

    w_transpose_kernel<<<dim3(NKV/32, DMODEL/32), dim3(32, 8), 0, hx.s2>>>(Wqkv);

    x_convert_kernel<<<NROWS*DMODEL/(8*256), 256>>>(x);
    cudaEventRecord(hx.eX, 0);
    cudaStreamWaitEvent(hx.s2, hx.eX, 0);

    kv_mma_kernel<<<dim3(NKV/128, NROWS/128), 256, 0, hx.s2>>>(bqkv);

    sel_copy_kernel<<<NROWS, 256>>>(x, sel_w, sel_b, temp, y);
    ranksel_kernel<<<dim3(SEQL/8, BATCH), 256>>>();
    qproj_kernel<<<dim3(12, 2, 12), 256>>>(x, Wqkv, bqkv);

    cudaEventRecord(hx.eK, hx.s2);
    cudaStreamWaitEvent(0, hx.eK, 0);

    attn_chunk_kernel<<<dim3(NCH, NH, BATCH), 256>>>();
    attn_combine_kernel<<<NQ*NH, HD>>>();
    outproj_kernel<<<dim3(12, 2, 12), 256>>>(out_w, out_b, y);
}